// round 1
// baseline (speedup 1.0000x reference)
#include <cuda_runtime.h>
#include <math.h>

// Problem constants
#define B_   32
#define T_   128
#define N_   64
#define F_   64      // per-part feature dim (D = H = 64)
#define DC_  128     // concat feature dim (x | h)
#define GO_  128     // gate output cols (2H)
#define CO_  64      // candidate output cols (H)

// Scratch (device globals: allocation-free)
__device__ float d_M[4 * 64 * 64];                 // M1=S0, M2=2S0^2-I, M3=S1, M4=2S1^2-I
__device__ float d_out0[B_ * T_ * N_ * F_];        // layer-0 hidden states per t (67MB)
__device__ float d_out1[B_ * T_ * N_ * F_];        // layer-1 hidden states per t
__device__ float d_RU[B_ * N_ * GO_];              // per-step gate activations (r|u)

// ---------------------------------------------------------------------------
// Precompute diffusion operator matrices.
// mats order in reference: [x, S0 x, (2S0^2-I)x, S1 x, (2S1^2-I)x]
// ---------------------------------------------------------------------------
__global__ void prep_kernel(const float* __restrict__ S0, const float* __restrict__ S1)
{
    __shared__ float Ss[64 * 64];
    const int s = blockIdx.x;
    const float* S = s ? S1 : S0;
    for (int i = threadIdx.x; i < 4096; i += blockDim.x) Ss[i] = S[i];
    __syncthreads();
    for (int i = threadIdx.x; i < 4096; i += blockDim.x) {
        int m = i >> 6, n = i & 63;
        float acc = 0.f;
        #pragma unroll 8
        for (int p = 0; p < 64; ++p) acc += Ss[m * 64 + p] * Ss[p * 64 + n];
        d_M[(2 * s) * 4096 + i]     = Ss[i];
        d_M[(2 * s + 1) * 4096 + i] = 2.f * acc - (m == n ? 1.f : 0.f);
    }
}

// ---------------------------------------------------------------------------
// Gate kernel: ru = sigmoid( sum_k M_k (u @ Wg_k) + bg ),  u = [x_t | h_{t-1}]
// grid (B, 4 column tiles of 32), block 128.
// Uses identity  (M_k u) W_k == M_k (u W_k): compute V_k = u @ W_k slice
// then apply M_k on the output side -> column tiles fully independent.
// ---------------------------------------------------------------------------
__global__ void __launch_bounds__(128) gate_kernel(
    const float* __restrict__ Xin, const float* __restrict__ W,
    const float* __restrict__ bias, int t, int layer)
{
    __shared__ float u_s[64 * 129];   // [n][d], pitch 129 = conflict-free
    __shared__ float V_s[64 * 36];    // current V_k tile [n][32], pitch 36

    const float* X  = layer ? d_out0 : Xin;   // layer input sequence
    const float* Hb = layer ? d_out1 : d_out0; // this layer's own outputs (h source)

    const int b = blockIdx.x, jt = blockIdx.y;
    const int tid = threadIdx.x;

    const float* xt = X + (size_t)(b * T_ + t) * N_ * F_;
    const float* hp = (t > 0) ? (Hb + (size_t)(b * T_ + t - 1) * N_ * F_) : (const float*)0;

    // Build u = [x_t | h]
    for (int i = tid; i < N_ * F_; i += 128) {
        int n = i >> 6, d = i & 63;
        u_s[n * 129 + d]      = xt[i];
        u_s[n * 129 + 64 + d] = hp ? hp[i] : 0.f;
    }
    __syncthreads();

    // V-phase mapping: rows {rg, rg+32}, 8 cols each
    const int rg = tid & 31;
    const int jg = tid >> 5;                 // 0..3
    const int jb = jt * 32 + jg * 8;

    // M-apply mapping: rows {mg, mg+16, mg+32, mg+48}, 4 cols
    const int ja = (tid & 7) * 4;
    const int mg = tid >> 3;                 // 0..15

    float y[4][4];                           // persistent output accumulators

    const float* u0 = u_s + rg * 129;
    const float* u1 = u_s + (rg + 32) * 129;

    for (int k = 0; k < 5; ++k) {
        float a0v[8], a1v[8];
        #pragma unroll
        for (int q = 0; q < 8; ++q) { a0v[q] = 0.f; a1v[q] = 0.f; }

        const float* Wk = W + (size_t)(k * 128) * GO_ + jb;  // Wg row-major (640,128)
        #pragma unroll 4
        for (int d = 0; d < 128; ++d) {
            float4 w0 = *(const float4*)(Wk + (size_t)d * GO_);
            float4 w1 = *(const float4*)(Wk + (size_t)d * GO_ + 4);
            float a0 = u0[d], a1 = u1[d];
            a0v[0] += a0 * w0.x; a0v[1] += a0 * w0.y; a0v[2] += a0 * w0.z; a0v[3] += a0 * w0.w;
            a0v[4] += a0 * w1.x; a0v[5] += a0 * w1.y; a0v[6] += a0 * w1.z; a0v[7] += a0 * w1.w;
            a1v[0] += a1 * w0.x; a1v[1] += a1 * w0.y; a1v[2] += a1 * w0.z; a1v[3] += a1 * w0.w;
            a1v[4] += a1 * w1.x; a1v[5] += a1 * w1.y; a1v[6] += a1 * w1.z; a1v[7] += a1 * w1.w;
        }
        __syncthreads();   // previous M-apply done reading V_s
        *(float4*)(V_s + rg * 36 + jg * 8)            = make_float4(a0v[0], a0v[1], a0v[2], a0v[3]);
        *(float4*)(V_s + rg * 36 + jg * 8 + 4)        = make_float4(a0v[4], a0v[5], a0v[6], a0v[7]);
        *(float4*)(V_s + (rg + 32) * 36 + jg * 8)     = make_float4(a1v[0], a1v[1], a1v[2], a1v[3]);
        *(float4*)(V_s + (rg + 32) * 36 + jg * 8 + 4) = make_float4(a1v[4], a1v[5], a1v[6], a1v[7]);
        __syncthreads();

        if (k == 0) {
            #pragma unroll
            for (int i = 0; i < 4; ++i) {
                float4 v = *(const float4*)(V_s + (mg + i * 16) * 36 + ja);
                y[i][0] = v.x; y[i][1] = v.y; y[i][2] = v.z; y[i][3] = v.w;
            }
        } else {
            const float* Mk = d_M + (k - 1) * 4096;
            #pragma unroll 2
            for (int m = 0; m < 64; m += 4) {
                float Mr[4][4];
                #pragma unroll
                for (int i = 0; i < 4; ++i) {
                    float4 mm = *(const float4*)(Mk + (mg + i * 16) * 64 + m);
                    Mr[i][0] = mm.x; Mr[i][1] = mm.y; Mr[i][2] = mm.z; Mr[i][3] = mm.w;
                }
                #pragma unroll
                for (int q = 0; q < 4; ++q) {
                    float4 v = *(const float4*)(V_s + (m + q) * 36 + ja);
                    #pragma unroll
                    for (int i = 0; i < 4; ++i) {
                        y[i][0] += Mr[i][q] * v.x;
                        y[i][1] += Mr[i][q] * v.y;
                        y[i][2] += Mr[i][q] * v.z;
                        y[i][3] += Mr[i][q] * v.w;
                    }
                }
            }
        }
    }

    // sigmoid + write RU
    float* ru = d_RU + b * (N_ * GO_);
    #pragma unroll
    for (int i = 0; i < 4; ++i) {
        int n = mg + i * 16;
        #pragma unroll
        for (int q = 0; q < 4; ++q) {
            int j = jt * 32 + ja + q;
            float v = y[i][q] + bias[j];
            ru[n * GO_ + j] = 1.f / (1.f + expf(-v));
        }
    }
}

// ---------------------------------------------------------------------------
// Candidate + state update kernel:
//   c = tanh( sum_k M_k (u_c @ Wc_k) + bc ),  u_c = [x_t | r*h]
//   h_t = u*h + (1-u)*c   -> written to out[layer][b][t]
// grid (B, 4 column tiles of 16), block 128.
// ---------------------------------------------------------------------------
__global__ void __launch_bounds__(128) cand_kernel(
    const float* __restrict__ Xin, const float* __restrict__ W,
    const float* __restrict__ bias, int t, int layer)
{
    __shared__ float u_s[64 * 129];
    __shared__ float V_s[64 * 20];

    const float* X  = layer ? d_out0 : Xin;
    float*       Hb = layer ? d_out1 : d_out0;

    const int b = blockIdx.x, jt = blockIdx.y;   // jt: 16-col tile
    const int tid = threadIdx.x;

    const float* xt = X + (size_t)(b * T_ + t) * N_ * F_;
    const float* hp = (t > 0) ? (Hb + (size_t)(b * T_ + t - 1) * N_ * F_) : (const float*)0;
    const float* ru = d_RU + b * (N_ * GO_);

    for (int i = tid; i < N_ * F_; i += 128) {
        int n = i >> 6, d = i & 63;
        u_s[n * 129 + d] = xt[i];
        float h = hp ? hp[i] : 0.f;
        u_s[n * 129 + 64 + d] = ru[n * GO_ + d] * h;   // r * h
    }
    __syncthreads();

    const int rg = tid & 31;
    const int jg = tid >> 5;                 // 0..3 -> 4 cols each
    const int jb = jt * 16 + jg * 4;

    const int ja = (tid & 3) * 4;            // M-apply 4-col group
    const int mg = tid >> 2;                 // 0..31 -> rows {mg, mg+32}

    float y[2][4];

    const float* u0 = u_s + rg * 129;
    const float* u1 = u_s + (rg + 32) * 129;

    for (int k = 0; k < 5; ++k) {
        float a0v[4] = {0.f, 0.f, 0.f, 0.f};
        float a1v[4] = {0.f, 0.f, 0.f, 0.f};

        const float* Wk = W + (size_t)(k * 128) * CO_ + jb;  // Wc row-major (640,64)
        #pragma unroll 4
        for (int d = 0; d < 128; ++d) {
            float4 w = *(const float4*)(Wk + (size_t)d * CO_);
            float a0 = u0[d], a1 = u1[d];
            a0v[0] += a0 * w.x; a0v[1] += a0 * w.y; a0v[2] += a0 * w.z; a0v[3] += a0 * w.w;
            a1v[0] += a1 * w.x; a1v[1] += a1 * w.y; a1v[2] += a1 * w.z; a1v[3] += a1 * w.w;
        }
        __syncthreads();
        *(float4*)(V_s + rg * 20 + jg * 4)        = make_float4(a0v[0], a0v[1], a0v[2], a0v[3]);
        *(float4*)(V_s + (rg + 32) * 20 + jg * 4) = make_float4(a1v[0], a1v[1], a1v[2], a1v[3]);
        __syncthreads();

        if (k == 0) {
            #pragma unroll
            for (int i = 0; i < 2; ++i) {
                float4 v = *(const float4*)(V_s + (mg + i * 32) * 20 + ja);
                y[i][0] = v.x; y[i][1] = v.y; y[i][2] = v.z; y[i][3] = v.w;
            }
        } else {
            const float* Mk = d_M + (k - 1) * 4096;
            #pragma unroll 2
            for (int m = 0; m < 64; m += 4) {
                float Mr[2][4];
                #pragma unroll
                for (int i = 0; i < 2; ++i) {
                    float4 mm = *(const float4*)(Mk + (mg + i * 32) * 64 + m);
                    Mr[i][0] = mm.x; Mr[i][1] = mm.y; Mr[i][2] = mm.z; Mr[i][3] = mm.w;
                }
                #pragma unroll
                for (int q = 0; q < 4; ++q) {
                    float4 v = *(const float4*)(V_s + (m + q) * 20 + ja);
                    #pragma unroll
                    for (int i = 0; i < 2; ++i) {
                        y[i][0] += Mr[i][q] * v.x;
                        y[i][1] += Mr[i][q] * v.y;
                        y[i][2] += Mr[i][q] * v.z;
                        y[i][3] += Mr[i][q] * v.w;
                    }
                }
            }
        }
    }

    // tanh, GRU update, store h_t
    float* hout = Hb + (size_t)(b * T_ + t) * N_ * F_;
    #pragma unroll
    for (int i = 0; i < 2; ++i) {
        int n = mg + i * 32;
        #pragma unroll
        for (int q = 0; q < 4; ++q) {
            int j = jt * 16 + ja + q;
            float c  = tanhf(y[i][q] + bias[j]);
            float ug = ru[n * GO_ + 64 + j];
            float h0 = hp ? hp[n * F_ + j] : 0.f;
            hout[n * F_ + j] = ug * h0 + (1.f - ug) * c;
        }
    }
}

// ---------------------------------------------------------------------------
// Final projection + node max-pool: out[b,c] = max_n ( relu(h_last[b,n,:]) @ Wp + bp )
// ---------------------------------------------------------------------------
__global__ void final_kernel(const int* __restrict__ lens,
                             const float* __restrict__ Wp, const float* __restrict__ bp,
                             float* __restrict__ out)
{
    __shared__ float red[64 * 4];
    const int b = blockIdx.x, n = threadIdx.x;
    int t = lens[b] - 1;
    t = t < 0 ? 0 : (t > T_ - 1 ? T_ - 1 : t);

    const float* h = d_out1 + (size_t)(b * T_ + t) * N_ * F_ + n * F_;
    float l0 = bp[0], l1 = bp[1], l2 = bp[2], l3 = bp[3];
    #pragma unroll 4
    for (int d = 0; d < 64; ++d) {
        float v = fmaxf(h[d], 0.f);
        l0 += v * Wp[d * 4 + 0];
        l1 += v * Wp[d * 4 + 1];
        l2 += v * Wp[d * 4 + 2];
        l3 += v * Wp[d * 4 + 3];
    }
    red[n * 4 + 0] = l0; red[n * 4 + 1] = l1; red[n * 4 + 2] = l2; red[n * 4 + 3] = l3;
    __syncthreads();
    for (int s = 32; s > 0; s >>= 1) {
        if (n < s) {
            #pragma unroll
            for (int c = 0; c < 4; ++c)
                red[n * 4 + c] = fmaxf(red[n * 4 + c], red[(n + s) * 4 + c]);
        }
        __syncthreads();
    }
    if (n < 4) out[b * 4 + n] = red[n];
}

// ---------------------------------------------------------------------------
extern "C" void kernel_launch(void* const* d_in, const int* in_sizes, int n_in,
                              void* d_out, int out_size)
{
    (void)in_sizes; (void)n_in; (void)out_size;
    const float* X   = (const float*)d_in[0];
    const int*   len = (const int*)  d_in[1];
    const float* S0  = (const float*)d_in[2];
    const float* S1  = (const float*)d_in[3];
    const float* Wg0 = (const float*)d_in[4];
    const float* bg0 = (const float*)d_in[5];
    const float* Wc0 = (const float*)d_in[6];
    const float* bc0 = (const float*)d_in[7];
    const float* Wg1 = (const float*)d_in[8];
    const float* bg1 = (const float*)d_in[9];
    const float* Wc1 = (const float*)d_in[10];
    const float* bc1 = (const float*)d_in[11];
    const float* Wp  = (const float*)d_in[12];
    const float* bp  = (const float*)d_in[13];
    float* out = (float*)d_out;

    prep_kernel<<<2, 256>>>(S0, S1);

    // Layer 0 scan
    for (int t = 0; t < T_; ++t) {
        gate_kernel<<<dim3(B_, 4), 128>>>(X, Wg0, bg0, t, 0);
        cand_kernel<<<dim3(B_, 4), 128>>>(X, Wc0, bc0, t, 0);
    }
    // Layer 1 scan (input = d_out0 selected inside by layer flag)
    for (int t = 0; t < T_; ++t) {
        gate_kernel<<<dim3(B_, 4), 128>>>(X, Wg1, bg1, t, 1);
        cand_kernel<<<dim3(B_, 4), 128>>>(X, Wc1, bc1, t, 1);
    }

    final_kernel<<<B_, 64>>>(len, Wp, bp, out);
}

// round 2
// speedup vs baseline: 2.1088x; 2.1088x over previous
#include <cuda_runtime.h>
#include <math.h>
#include <stdint.h>

#define B_ 32
#define T_ 128

// Scratch (device globals: allocation-free)
__device__ float d_M[4 * 4096];                // M1=S0, M2=2S0^2-I, M3=S1, M4=2S1^2-I
__device__ float d_out0[B_ * T_ * 64 * 64];    // layer-0 hidden states per t
__device__ float d_last[B_ * 64 * 64];         // layer-1 h at last relevant timestep

// ---- dynamic smem layout (float offsets) ----
#define WG_OFF   0          // 640*32 = 20480   gate weight slice
#define WC_OFF   20480      // 640*16 = 10240   cand weight slice
#define U_OFF    30720      // 64*129 =  8256   u = [x | h] (pitch 129)
#define H_OFF    38976      // 64*65  =  4160   full h (pitch 65)
#define V_OFF    43136      // 64*36  =  2304   V_k staging (pitch 36 / 20)
#define RST_OFF  45440      // 64*17  =  1088   r stage (local 16 cols)
#define UGS_OFF  46528      // 64*17  =  1088   u-gate local 16 cols
#define HST_OFF  47616      // 64*17  =  1088   h stage
#define MB_OFF   48704      // 4096             current M_k (cp.async prefetch)
#define SMEM_FLOATS 52800
#define SMEM_BYTES (SMEM_FLOATS * 4)           // 211200 B

__device__ __forceinline__ uint32_t s_u32(const void* p) {
    return (uint32_t)__cvta_generic_to_shared(p);
}
__device__ __forceinline__ uint32_t mapa_rank(uint32_t a, uint32_t r) {
    uint32_t o;
    asm("mapa.shared::cluster.u32 %0, %1, %2;" : "=r"(o) : "r"(a), "r"(r));
    return o;
}
__device__ __forceinline__ float ldc_f32(uint32_t a) {
    float v;
    asm volatile("ld.shared::cluster.f32 %0, [%1];" : "=f"(v) : "r"(a));
    return v;
}
__device__ __forceinline__ void cp16(float* dst, const float* src) {
    asm volatile("cp.async.cg.shared.global [%0], [%1], 16;"
                 :: "r"(s_u32(dst)), "l"(src));
}
#define CP_COMMIT() asm volatile("cp.async.commit_group;")
#define CP_WAIT()   asm volatile("cp.async.wait_group 0;")
#define CLUSTER_SYNC() do { \
    asm volatile("barrier.cluster.arrive.aligned;" ::: "memory"); \
    asm volatile("barrier.cluster.wait.aligned;"   ::: "memory"); } while (0)

// ---------------------------------------------------------------------------
// Precompute diffusion operators. mats order: [x, S0 x, (2S0^2-I)x, S1 x, (2S1^2-I)x]
// ---------------------------------------------------------------------------
__global__ void prep_kernel(const float* __restrict__ S0, const float* __restrict__ S1)
{
    __shared__ float Ss[64 * 64];
    const int s = blockIdx.x;
    const float* S = s ? S1 : S0;
    for (int i = threadIdx.x; i < 4096; i += blockDim.x) Ss[i] = S[i];
    __syncthreads();
    for (int i = threadIdx.x; i < 4096; i += blockDim.x) {
        int m = i >> 6, n = i & 63;
        float acc = 0.f;
        #pragma unroll 8
        for (int p = 0; p < 64; ++p) acc += Ss[m * 64 + p] * Ss[p * 64 + n];
        d_M[(2 * s) * 4096 + i]     = Ss[i];
        d_M[(2 * s + 1) * 4096 + i] = 2.f * acc - (m == n ? 1.f : 0.f);
    }
}

// ---------------------------------------------------------------------------
// Persistent per-layer scan. Grid = 128 CTAs = 32 batches x cluster(4).
// Rank j owns gate cols {j*16..j*16+15} U {64+j*16..64+j*16+15} and cand cols
// {j*16..j*16+15}. Weights live in SMEM for the whole scan; per-step r/h tiles
// are exchanged over DSMEM with 2 cluster syncs per step.
// Uses (M_k u) W_k == M_k (u W_k): V_k = u @ Wk slice in SMEM, then M_k applied
// output-side from a cp.async-prefetched SMEM copy of M_k.
// ---------------------------------------------------------------------------
extern __shared__ float smem[];

__global__ void __launch_bounds__(256, 1) __cluster_dims__(4, 1, 1)
scan_kernel(const float* __restrict__ Xin,
            const float* __restrict__ Wg, const float* __restrict__ bg,
            const float* __restrict__ Wc, const float* __restrict__ bc,
            const int* __restrict__ lens, int layer)
{
    float* wg  = smem + WG_OFF;
    float* wc  = smem + WC_OFF;
    float* u_s = smem + U_OFF;
    float* h_s = smem + H_OFF;
    float* V_s = smem + V_OFF;
    float* rst = smem + RST_OFF;
    float* ugs = smem + UGS_OFF;
    float* hst = smem + HST_OFF;
    float* mb  = smem + MB_OFF;

    const int tid = threadIdx.x;
    const int b = blockIdx.x >> 2;
    const int j = blockIdx.x & 3;   // == cluster_ctarank for cluster_dims (4,1,1)

    // --- one-time weight slice load into SMEM ---
    for (int i = tid; i < 640 * 32; i += 256) {
        int d = i >> 5, c = i & 31;
        int g = (c < 16) ? (j * 16 + c) : (64 + j * 16 + (c - 16));
        wg[i] = Wg[d * 128 + g];
    }
    for (int i = tid; i < 640 * 16; i += 256) {
        int d = i >> 4, c = i & 15;
        wc[i] = Wc[d * 64 + j * 16 + c];
    }

    const int rg  = tid & 31;        // V-phase row
    const int jg  = tid >> 5;        // V-phase col group (0..7)
    const int mg  = tid >> 3;        // M-apply row (0..31)
    const int ja4 = (tid & 7) * 4;   // gate M-apply col group
    const int ja2 = (tid & 7) * 2;   // cand M-apply col group

    float bgv[4], bcv[2];
    #pragma unroll
    for (int q = 0; q < 4; ++q) {
        int c = ja4 + q;
        int g = (c < 16) ? (j * 16 + c) : (64 + j * 16 + (c - 16));
        bgv[q] = bg[g];
    }
    bcv[0] = bc[j * 16 + ja2];
    bcv[1] = bc[j * 16 + ja2 + 1];

    const float* X = layer ? d_out0 : Xin;
    const float* xbase = X + (size_t)b * T_ * 4096;

    // --- init u = [x_0 | 0], h = 0 ---
    for (int i = tid; i < 4096; i += 256) {
        int n = i >> 6, d = i & 63;
        u_s[n * 129 + d]      = xbase[i];
        u_s[n * 129 + 64 + d] = 0.f;
        h_s[n * 65 + d]       = 0.f;
    }

    int idx_t = lens[b] - 1;
    idx_t = idx_t < 0 ? 0 : (idx_t > T_ - 1 ? T_ - 1 : idx_t);

    uint32_t rbase[4], hbase[4];
    #pragma unroll
    for (int r = 0; r < 4; ++r) {
        rbase[r] = mapa_rank(s_u32(rst), (uint32_t)r);
        hbase[r] = mapa_rank(s_u32(hst), (uint32_t)r);
    }

    const float* u0 = u_s + rg * 129;
    const float* u1 = u_s + (rg + 32) * 129;

    for (int t = 0; t < T_; ++t) {
        __syncthreads();

        // ===================== GATE =====================
        float y[2][4];
        for (int k = 0; k < 5; ++k) {
            if (k == 0) {   // prefetch M_0 (used at k=1) while V_0 computes
                for (int i = tid; i < 1024; i += 256) cp16(mb + i * 4, d_M + i * 4);
                CP_COMMIT();
            }
            float a0v[4] = {0, 0, 0, 0}, a1v[4] = {0, 0, 0, 0};
            const float* Wk = wg + (k * 128) * 32 + jg * 4;
            #pragma unroll 4
            for (int d = 0; d < 128; ++d) {
                float4 w = *(const float4*)(Wk + d * 32);   // uniform -> smem broadcast
                float a0 = u0[d], a1 = u1[d];
                a0v[0] += a0 * w.x; a0v[1] += a0 * w.y; a0v[2] += a0 * w.z; a0v[3] += a0 * w.w;
                a1v[0] += a1 * w.x; a1v[1] += a1 * w.y; a1v[2] += a1 * w.z; a1v[3] += a1 * w.w;
            }
            __syncthreads();
            *(float4*)(V_s + rg * 36 + jg * 4)        = make_float4(a0v[0], a0v[1], a0v[2], a0v[3]);
            *(float4*)(V_s + (rg + 32) * 36 + jg * 4) = make_float4(a1v[0], a1v[1], a1v[2], a1v[3]);
            __syncthreads();

            if (k == 0) {
                float4 v0 = *(const float4*)(V_s + mg * 36 + ja4);
                float4 v1 = *(const float4*)(V_s + (mg + 32) * 36 + ja4);
                y[0][0] = v0.x; y[0][1] = v0.y; y[0][2] = v0.z; y[0][3] = v0.w;
                y[1][0] = v1.x; y[1][1] = v1.y; y[1][2] = v1.z; y[1][3] = v1.w;
            } else {
                CP_WAIT();
                __syncthreads();
                #pragma unroll 4
                for (int m = 0; m < 64; m += 4) {
                    float4 mA = *(const float4*)(mb + mg * 64 + m);
                    float4 mB = *(const float4*)(mb + (mg + 32) * 64 + m);
                    float4 v;
                    v = *(const float4*)(V_s + (m + 0) * 36 + ja4);
                    y[0][0] += mA.x * v.x; y[0][1] += mA.x * v.y; y[0][2] += mA.x * v.z; y[0][3] += mA.x * v.w;
                    y[1][0] += mB.x * v.x; y[1][1] += mB.x * v.y; y[1][2] += mB.x * v.z; y[1][3] += mB.x * v.w;
                    v = *(const float4*)(V_s + (m + 1) * 36 + ja4);
                    y[0][0] += mA.y * v.x; y[0][1] += mA.y * v.y; y[0][2] += mA.y * v.z; y[0][3] += mA.y * v.w;
                    y[1][0] += mB.y * v.x; y[1][1] += mB.y * v.y; y[1][2] += mB.y * v.z; y[1][3] += mB.y * v.w;
                    v = *(const float4*)(V_s + (m + 2) * 36 + ja4);
                    y[0][0] += mA.z * v.x; y[0][1] += mA.z * v.y; y[0][2] += mA.z * v.z; y[0][3] += mA.z * v.w;
                    y[1][0] += mB.z * v.x; y[1][1] += mB.z * v.y; y[1][2] += mB.z * v.z; y[1][3] += mB.z * v.w;
                    v = *(const float4*)(V_s + (m + 3) * 36 + ja4);
                    y[0][0] += mA.w * v.x; y[0][1] += mA.w * v.y; y[0][2] += mA.w * v.z; y[0][3] += mA.w * v.w;
                    y[1][0] += mB.w * v.x; y[1][1] += mB.w * v.y; y[1][2] += mB.w * v.z; y[1][3] += mB.w * v.w;
                }
                __syncthreads();                 // mb reads done before refill
                if (k < 4) {                     // prefetch M_k (used at k+1)
                    for (int i = tid; i < 1024; i += 256)
                        cp16(mb + i * 4, d_M + k * 4096 + i * 4);
                    CP_COMMIT();
                }
            }
        }

        // sigmoid -> stage r (local cols 0..15) and u-gate (local cols 16..31)
        #pragma unroll
        for (int i2 = 0; i2 < 2; ++i2) {
            int n = mg + i2 * 32;
            #pragma unroll
            for (int q = 0; q < 4; ++q) {
                int c = ja4 + q;
                float v = 1.f / (1.f + expf(-(y[i2][q] + bgv[q])));
                if (c < 16) rst[n * 17 + c] = v;
                else        ugs[n * 17 + (c - 16)] = v;
            }
        }

        CLUSTER_SYNC();   // S1: r stages visible cluster-wide

        // build u_c: u[:,64:] = r * h  (r gathered from all 4 ranks via DSMEM)
        #pragma unroll 4
        for (int i = tid; i < 4096; i += 256) {
            int n = i >> 6, d = i & 63;
            float r = ldc_f32(rbase[d >> 4] + (uint32_t)(n * 17 + (d & 15)) * 4);
            u_s[n * 129 + 64 + d] = r * h_s[n * 65 + d];
        }
        __syncthreads();

        // ===================== CAND =====================
        const int jc = jg * 2;
        float y2[2][2];
        for (int k = 0; k < 5; ++k) {
            if (k == 0) {
                for (int i = tid; i < 1024; i += 256) cp16(mb + i * 4, d_M + i * 4);
                CP_COMMIT();
            }
            float a0v[2] = {0, 0}, a1v[2] = {0, 0};
            const float* Wk = wc + (k * 128) * 16 + jc;
            #pragma unroll 4
            for (int d = 0; d < 128; ++d) {
                float2 w = *(const float2*)(Wk + d * 16);
                float a0 = u0[d], a1 = u1[d];
                a0v[0] += a0 * w.x; a0v[1] += a0 * w.y;
                a1v[0] += a1 * w.x; a1v[1] += a1 * w.y;
            }
            __syncthreads();
            *(float2*)(V_s + rg * 20 + jc)        = make_float2(a0v[0], a0v[1]);
            *(float2*)(V_s + (rg + 32) * 20 + jc) = make_float2(a1v[0], a1v[1]);
            __syncthreads();

            if (k == 0) {
                float2 v0 = *(const float2*)(V_s + mg * 20 + ja2);
                float2 v1 = *(const float2*)(V_s + (mg + 32) * 20 + ja2);
                y2[0][0] = v0.x; y2[0][1] = v0.y;
                y2[1][0] = v1.x; y2[1][1] = v1.y;
            } else {
                CP_WAIT();
                __syncthreads();
                #pragma unroll 4
                for (int m = 0; m < 64; m += 4) {
                    float4 mA = *(const float4*)(mb + mg * 64 + m);
                    float4 mB = *(const float4*)(mb + (mg + 32) * 64 + m);
                    float2 v;
                    v = *(const float2*)(V_s + (m + 0) * 20 + ja2);
                    y2[0][0] += mA.x * v.x; y2[0][1] += mA.x * v.y;
                    y2[1][0] += mB.x * v.x; y2[1][1] += mB.x * v.y;
                    v = *(const float2*)(V_s + (m + 1) * 20 + ja2);
                    y2[0][0] += mA.y * v.x; y2[0][1] += mA.y * v.y;
                    y2[1][0] += mB.y * v.x; y2[1][1] += mB.y * v.y;
                    v = *(const float2*)(V_s + (m + 2) * 20 + ja2);
                    y2[0][0] += mA.z * v.x; y2[0][1] += mA.z * v.y;
                    y2[1][0] += mB.z * v.x; y2[1][1] += mB.z * v.y;
                    v = *(const float2*)(V_s + (m + 3) * 20 + ja2);
                    y2[0][0] += mA.w * v.x; y2[0][1] += mA.w * v.y;
                    y2[1][0] += mB.w * v.x; y2[1][1] += mB.w * v.y;
                }
                __syncthreads();
                if (k < 4) {
                    for (int i = tid; i < 1024; i += 256)
                        cp16(mb + i * 4, d_M + k * 4096 + i * 4);
                    CP_COMMIT();
                }
            }
        }

        // GRU update: h_n = u*h + (1-u)*tanh(c); stage + gmem out
        float* hout0 = d_out0 + ((size_t)(b * T_ + t)) * 4096;
        #pragma unroll
        for (int i2 = 0; i2 < 2; ++i2) {
            int n = mg + i2 * 32;
            #pragma unroll
            for (int q = 0; q < 2; ++q) {
                int cl  = ja2 + q;
                int col = j * 16 + cl;
                float c  = tanhf(y2[i2][q] + bcv[q]);
                float ug = ugs[n * 17 + cl];
                float h0 = h_s[n * 65 + col];
                float hn = ug * h0 + (1.f - ug) * c;
                hst[n * 17 + cl] = hn;
                if (layer == 0)          hout0[n * 64 + col] = hn;
                else if (t == idx_t)     d_last[(size_t)b * 4096 + n * 64 + col] = hn;
            }
        }

        CLUSTER_SYNC();   // S2: h stages visible cluster-wide

        // assemble full h, prime u for next step
        const float* xnext = (t + 1 < T_) ? (xbase + (size_t)(t + 1) * 4096) : 0;
        #pragma unroll 4
        for (int i = tid; i < 4096; i += 256) {
            int n = i >> 6, d = i & 63;
            float hv = ldc_f32(hbase[d >> 4] + (uint32_t)(n * 17 + (d & 15)) * 4);
            h_s[n * 65 + d]       = hv;
            u_s[n * 129 + 64 + d] = hv;
            if (xnext) u_s[n * 129 + d] = xnext[i];
        }
    }
    CLUSTER_SYNC();   // no CTA exits while peers may still read its DSMEM
}

// ---------------------------------------------------------------------------
// Final projection + node max-pool
// ---------------------------------------------------------------------------
__global__ void final_kernel(const float* __restrict__ Wp, const float* __restrict__ bp,
                             float* __restrict__ out)
{
    __shared__ float red[64 * 4];
    const int b = blockIdx.x, n = threadIdx.x;
    const float* h = d_last + (size_t)b * 4096 + n * 64;
    float l0 = bp[0], l1 = bp[1], l2 = bp[2], l3 = bp[3];
    #pragma unroll 8
    for (int d = 0; d < 64; ++d) {
        float v = fmaxf(h[d], 0.f);
        l0 += v * Wp[d * 4 + 0];
        l1 += v * Wp[d * 4 + 1];
        l2 += v * Wp[d * 4 + 2];
        l3 += v * Wp[d * 4 + 3];
    }
    red[n * 4 + 0] = l0; red[n * 4 + 1] = l1; red[n * 4 + 2] = l2; red[n * 4 + 3] = l3;
    __syncthreads();
    for (int s = 32; s > 0; s >>= 1) {
        if (n < s) {
            #pragma unroll
            for (int c = 0; c < 4; ++c)
                red[n * 4 + c] = fmaxf(red[n * 4 + c], red[(n + s) * 4 + c]);
        }
        __syncthreads();
    }
    if (n < 4) out[b * 4 + n] = red[n];
}

// ---------------------------------------------------------------------------
extern "C" void kernel_launch(void* const* d_in, const int* in_sizes, int n_in,
                              void* d_out, int out_size)
{
    (void)in_sizes; (void)n_in; (void)out_size;
    const float* X   = (const float*)d_in[0];
    const int*   len = (const int*)  d_in[1];
    const float* S0  = (const float*)d_in[2];
    const float* S1  = (const float*)d_in[3];
    const float* Wg0 = (const float*)d_in[4];
    const float* bg0 = (const float*)d_in[5];
    const float* Wc0 = (const float*)d_in[6];
    const float* bc0 = (const float*)d_in[7];
    const float* Wg1 = (const float*)d_in[8];
    const float* bg1 = (const float*)d_in[9];
    const float* Wc1 = (const float*)d_in[10];
    const float* bc1 = (const float*)d_in[11];
    const float* Wp  = (const float*)d_in[12];
    const float* bp  = (const float*)d_in[13];
    float* out = (float*)d_out;

    cudaFuncSetAttribute(scan_kernel, cudaFuncAttributeMaxDynamicSharedMemorySize, SMEM_BYTES);

    prep_kernel<<<2, 256>>>(S0, S1);
    scan_kernel<<<128, 256, SMEM_BYTES>>>(X, Wg0, bg0, Wc0, bc0, len, 0);
    scan_kernel<<<128, 256, SMEM_BYTES>>>(X, Wg1, bg1, Wc1, bc1, len, 1);
    final_kernel<<<B_, 64>>>(Wp, bp, out);
}

// round 3
// speedup vs baseline: 2.1110x; 1.0011x over previous
#include <cuda_runtime.h>
#include <math.h>
#include <stdint.h>

#define B_ 32
#define T_ 128

// Scratch (device globals: allocation-free)
__device__ float d_M[4 * 4096];                // M1=S0, M2=2S0^2-I, M3=S1, M4=2S1^2-I
__device__ float d_out0[B_ * T_ * 64 * 64];    // layer-0 hidden states per t
__device__ float d_last[B_ * 64 * 64];         // layer-1 h at last relevant timestep

// ---- dynamic smem layout (float offsets) ----
#define WG_OFF   0          // 640*32 = 20480   gate weight slice
#define WC_OFF   20480      // 640*16 = 10240   cand weight slice
#define U_OFF    30720      // 64*129 =  8256   u = [x | h] (pitch 129)
#define H_OFF    38976      // 64*65  =  4160   full h (pitch 65)
#define V_OFF    43136      // 64*36  =  2304   V_k staging (pitch 36 / 20)
#define RST_OFF  45440      // 64*17  =  1088   r stage (local 16 cols)
#define UGS_OFF  46528      // 64*17  =  1088   u-gate local 16 cols
#define HST_OFF  47616      // 64*17  =  1088   h stage
#define MB_OFF   48704      // 4096             current M_k (cp.async prefetch)
#define SMEM_FLOATS 52800
#define SMEM_BYTES (SMEM_FLOATS * 4)           // 211200 B

__device__ __forceinline__ uint32_t s_u32(const void* p) {
    return (uint32_t)__cvta_generic_to_shared(p);
}
__device__ __forceinline__ uint32_t mapa_rank(uint32_t a, uint32_t r) {
    uint32_t o;
    asm("mapa.shared::cluster.u32 %0, %1, %2;" : "=r"(o) : "r"(a), "r"(r));
    return o;
}
__device__ __forceinline__ float ldc_f32(uint32_t a) {
    float v;
    asm volatile("ld.shared::cluster.f32 %0, [%1];" : "=f"(v) : "r"(a));
    return v;
}
__device__ __forceinline__ void cp16(float* dst, const float* src) {
    asm volatile("cp.async.cg.shared.global [%0], [%1], 16;"
                 :: "r"(s_u32(dst)), "l"(src));
}
#define CP_COMMIT() asm volatile("cp.async.commit_group;")
#define CP_WAIT()   asm volatile("cp.async.wait_group 0;")
#define CLUSTER_SYNC() do { \
    asm volatile("barrier.cluster.arrive.aligned;" ::: "memory"); \
    asm volatile("barrier.cluster.wait.aligned;"   ::: "memory"); } while (0)

// ---------------------------------------------------------------------------
// Precompute diffusion operators. mats order: [x, S0 x, (2S0^2-I)x, S1 x, (2S1^2-I)x]
// ---------------------------------------------------------------------------
__global__ void prep_kernel(const float* __restrict__ S0, const float* __restrict__ S1)
{
    __shared__ float Ss[64 * 64];
    const int s = blockIdx.x;
    const float* S = s ? S1 : S0;
    for (int i = threadIdx.x; i < 4096; i += blockDim.x) Ss[i] = S[i];
    __syncthreads();
    for (int i = threadIdx.x; i < 4096; i += blockDim.x) {
        int m = i >> 6, n = i & 63;
        float acc = 0.f;
        #pragma unroll 8
        for (int p = 0; p < 64; ++p) acc += Ss[m * 64 + p] * Ss[p * 64 + n];
        d_M[(2 * s) * 4096 + i]     = Ss[i];
        d_M[(2 * s + 1) * 4096 + i] = 2.f * acc - (m == n ? 1.f : 0.f);
    }
}

// ---------------------------------------------------------------------------
// Persistent per-layer scan. Grid = 128 CTAs = 32 batches x cluster(4).
// Rank j owns gate cols {j*16..j*16+15} U {64+j*16..64+j*16+15} and cand cols
// {j*16..j*16+15}. Weights live in SMEM for the whole scan; per-step r/h tiles
// are exchanged over DSMEM with 2 cluster syncs per step.
// Uses (M_k u) W_k == M_k (u W_k): V_k = u @ Wk slice in SMEM, then M_k applied
// output-side from a cp.async-prefetched SMEM copy of M_k.
// ---------------------------------------------------------------------------
extern __shared__ float smem[];

__global__ void __launch_bounds__(256, 1) __cluster_dims__(4, 1, 1)
scan_kernel(const float* __restrict__ Xin,
            const float* __restrict__ Wg, const float* __restrict__ bg,
            const float* __restrict__ Wc, const float* __restrict__ bc,
            const int* __restrict__ lens, int layer)
{
    float* wg  = smem + WG_OFF;
    float* wc  = smem + WC_OFF;
    float* u_s = smem + U_OFF;
    float* h_s = smem + H_OFF;
    float* V_s = smem + V_OFF;
    float* rst = smem + RST_OFF;
    float* ugs = smem + UGS_OFF;
    float* hst = smem + HST_OFF;
    float* mb  = smem + MB_OFF;

    const int tid = threadIdx.x;
    const int b = blockIdx.x >> 2;
    const int j = blockIdx.x & 3;   // == cluster_ctarank for cluster_dims (4,1,1)

    // --- one-time weight slice load into SMEM ---
    for (int i = tid; i < 640 * 32; i += 256) {
        int d = i >> 5, c = i & 31;
        int g = (c < 16) ? (j * 16 + c) : (64 + j * 16 + (c - 16));
        wg[i] = Wg[d * 128 + g];
    }
    for (int i = tid; i < 640 * 16; i += 256) {
        int d = i >> 4, c = i & 15;
        wc[i] = Wc[d * 64 + j * 16 + c];
    }

    const int rg  = tid & 31;        // V-phase row
    const int jg  = tid >> 5;        // V-phase col group (0..7)
    const int mg  = tid >> 3;        // M-apply row (0..31)
    const int ja4 = (tid & 7) * 4;   // gate M-apply col group
    const int ja2 = (tid & 7) * 2;   // cand M-apply col group

    float bgv[4], bcv[2];
    #pragma unroll
    for (int q = 0; q < 4; ++q) {
        int c = ja4 + q;
        int g = (c < 16) ? (j * 16 + c) : (64 + j * 16 + (c - 16));
        bgv[q] = bg[g];
    }
    bcv[0] = bc[j * 16 + ja2];
    bcv[1] = bc[j * 16 + ja2 + 1];

    const float* X = layer ? d_out0 : Xin;
    const float* xbase = X + (size_t)b * T_ * 4096;

    // --- init u = [x_0 | 0], h = 0 ---
    for (int i = tid; i < 4096; i += 256) {
        int n = i >> 6, d = i & 63;
        u_s[n * 129 + d]      = xbase[i];
        u_s[n * 129 + 64 + d] = 0.f;
        h_s[n * 65 + d]       = 0.f;
    }

    int idx_t = lens[b] - 1;
    idx_t = idx_t < 0 ? 0 : (idx_t > T_ - 1 ? T_ - 1 : idx_t);

    uint32_t rbase[4], hbase[4];
    #pragma unroll
    for (int r = 0; r < 4; ++r) {
        rbase[r] = mapa_rank(s_u32(rst), (uint32_t)r);
        hbase[r] = mapa_rank(s_u32(hst), (uint32_t)r);
    }

    const float* u0 = u_s + rg * 129;
    const float* u1 = u_s + (rg + 32) * 129;

    for (int t = 0; t < T_; ++t) {
        __syncthreads();

        // ===================== GATE =====================
        float y[2][4];
        for (int k = 0; k < 5; ++k) {
            if (k == 0) {   // prefetch M_0 (used at k=1) while V_0 computes
                for (int i = tid; i < 1024; i += 256) cp16(mb + i * 4, d_M + i * 4);
                CP_COMMIT();
            }
            float a0v[4] = {0, 0, 0, 0}, a1v[4] = {0, 0, 0, 0};
            const float* Wk = wg + (k * 128) * 32 + jg * 4;
            #pragma unroll 4
            for (int d = 0; d < 128; ++d) {
                float4 w = *(const float4*)(Wk + d * 32);   // uniform -> smem broadcast
                float a0 = u0[d], a1 = u1[d];
                a0v[0] += a0 * w.x; a0v[1] += a0 * w.y; a0v[2] += a0 * w.z; a0v[3] += a0 * w.w;
                a1v[0] += a1 * w.x; a1v[1] += a1 * w.y; a1v[2] += a1 * w.z; a1v[3] += a1 * w.w;
            }
            __syncthreads();
            *(float4*)(V_s + rg * 36 + jg * 4)        = make_float4(a0v[0], a0v[1], a0v[2], a0v[3]);
            *(float4*)(V_s + (rg + 32) * 36 + jg * 4) = make_float4(a1v[0], a1v[1], a1v[2], a1v[3]);
            __syncthreads();

            if (k == 0) {
                float4 v0 = *(const float4*)(V_s + mg * 36 + ja4);
                float4 v1 = *(const float4*)(V_s + (mg + 32) * 36 + ja4);
                y[0][0] = v0.x; y[0][1] = v0.y; y[0][2] = v0.z; y[0][3] = v0.w;
                y[1][0] = v1.x; y[1][1] = v1.y; y[1][2] = v1.z; y[1][3] = v1.w;
            } else {
                CP_WAIT();
                __syncthreads();
                #pragma unroll 4
                for (int m = 0; m < 64; m += 4) {
                    float4 mA = *(const float4*)(mb + mg * 64 + m);
                    float4 mB = *(const float4*)(mb + (mg + 32) * 64 + m);
                    float4 v;
                    v = *(const float4*)(V_s + (m + 0) * 36 + ja4);
                    y[0][0] += mA.x * v.x; y[0][1] += mA.x * v.y; y[0][2] += mA.x * v.z; y[0][3] += mA.x * v.w;
                    y[1][0] += mB.x * v.x; y[1][1] += mB.x * v.y; y[1][2] += mB.x * v.z; y[1][3] += mB.x * v.w;
                    v = *(const float4*)(V_s + (m + 1) * 36 + ja4);
                    y[0][0] += mA.y * v.x; y[0][1] += mA.y * v.y; y[0][2] += mA.y * v.z; y[0][3] += mA.y * v.w;
                    y[1][0] += mB.y * v.x; y[1][1] += mB.y * v.y; y[1][2] += mB.y * v.z; y[1][3] += mB.y * v.w;
                    v = *(const float4*)(V_s + (m + 2) * 36 + ja4);
                    y[0][0] += mA.z * v.x; y[0][1] += mA.z * v.y; y[0][2] += mA.z * v.z; y[0][3] += mA.z * v.w;
                    y[1][0] += mB.z * v.x; y[1][1] += mB.z * v.y; y[1][2] += mB.z * v.z; y[1][3] += mB.z * v.w;
                    v = *(const float4*)(V_s + (m + 3) * 36 + ja4);
                    y[0][0] += mA.w * v.x; y[0][1] += mA.w * v.y; y[0][2] += mA.w * v.z; y[0][3] += mA.w * v.w;
                    y[1][0] += mB.w * v.x; y[1][1] += mB.w * v.y; y[1][2] += mB.w * v.z; y[1][3] += mB.w * v.w;
                }
                __syncthreads();                 // mb reads done before refill
                if (k < 4) {                     // prefetch M_k (used at k+1)
                    for (int i = tid; i < 1024; i += 256)
                        cp16(mb + i * 4, d_M + k * 4096 + i * 4);
                    CP_COMMIT();
                }
            }
        }

        // sigmoid -> stage r (local cols 0..15) and u-gate (local cols 16..31)
        #pragma unroll
        for (int i2 = 0; i2 < 2; ++i2) {
            int n = mg + i2 * 32;
            #pragma unroll
            for (int q = 0; q < 4; ++q) {
                int c = ja4 + q;
                float v = 1.f / (1.f + expf(-(y[i2][q] + bgv[q])));
                if (c < 16) rst[n * 17 + c] = v;
                else        ugs[n * 17 + (c - 16)] = v;
            }
        }

        CLUSTER_SYNC();   // S1: r stages visible cluster-wide

        // build u_c: u[:,64:] = r * h  (r gathered from all 4 ranks via DSMEM)
        #pragma unroll 4
        for (int i = tid; i < 4096; i += 256) {
            int n = i >> 6, d = i & 63;
            float r = ldc_f32(rbase[d >> 4] + (uint32_t)(n * 17 + (d & 15)) * 4);
            u_s[n * 129 + 64 + d] = r * h_s[n * 65 + d];
        }
        __syncthreads();

        // ===================== CAND =====================
        const int jc = jg * 2;
        float y2[2][2];
        for (int k = 0; k < 5; ++k) {
            if (k == 0) {
                for (int i = tid; i < 1024; i += 256) cp16(mb + i * 4, d_M + i * 4);
                CP_COMMIT();
            }
            float a0v[2] = {0, 0}, a1v[2] = {0, 0};
            const float* Wk = wc + (k * 128) * 16 + jc;
            #pragma unroll 4
            for (int d = 0; d < 128; ++d) {
                float2 w = *(const float2*)(Wk + d * 16);
                float a0 = u0[d], a1 = u1[d];
                a0v[0] += a0 * w.x; a0v[1] += a0 * w.y;
                a1v[0] += a1 * w.x; a1v[1] += a1 * w.y;
            }
            __syncthreads();
            *(float2*)(V_s + rg * 20 + jc)        = make_float2(a0v[0], a0v[1]);
            *(float2*)(V_s + (rg + 32) * 20 + jc) = make_float2(a1v[0], a1v[1]);
            __syncthreads();

            if (k == 0) {
                float2 v0 = *(const float2*)(V_s + mg * 20 + ja2);
                float2 v1 = *(const float2*)(V_s + (mg + 32) * 20 + ja2);
                y2[0][0] = v0.x; y2[0][1] = v0.y;
                y2[1][0] = v1.x; y2[1][1] = v1.y;
            } else {
                CP_WAIT();
                __syncthreads();
                #pragma unroll 4
                for (int m = 0; m < 64; m += 4) {
                    float4 mA = *(const float4*)(mb + mg * 64 + m);
                    float4 mB = *(const float4*)(mb + (mg + 32) * 64 + m);
                    float2 v;
                    v = *(const float2*)(V_s + (m + 0) * 20 + ja2);
                    y2[0][0] += mA.x * v.x; y2[0][1] += mA.x * v.y;
                    y2[1][0] += mB.x * v.x; y2[1][1] += mB.x * v.y;
                    v = *(const float2*)(V_s + (m + 1) * 20 + ja2);
                    y2[0][0] += mA.y * v.x; y2[0][1] += mA.y * v.y;
                    y2[1][0] += mB.y * v.x; y2[1][1] += mB.y * v.y;
                    v = *(const float2*)(V_s + (m + 2) * 20 + ja2);
                    y2[0][0] += mA.z * v.x; y2[0][1] += mA.z * v.y;
                    y2[1][0] += mB.z * v.x; y2[1][1] += mB.z * v.y;
                    v = *(const float2*)(V_s + (m + 3) * 20 + ja2);
                    y2[0][0] += mA.w * v.x; y2[0][1] += mA.w * v.y;
                    y2[1][0] += mB.w * v.x; y2[1][1] += mB.w * v.y;
                }
                __syncthreads();
                if (k < 4) {
                    for (int i = tid; i < 1024; i += 256)
                        cp16(mb + i * 4, d_M + k * 4096 + i * 4);
                    CP_COMMIT();
                }
            }
        }

        // GRU update: h_n = u*h + (1-u)*tanh(c); stage + gmem out
        float* hout0 = d_out0 + ((size_t)(b * T_ + t)) * 4096;
        #pragma unroll
        for (int i2 = 0; i2 < 2; ++i2) {
            int n = mg + i2 * 32;
            #pragma unroll
            for (int q = 0; q < 2; ++q) {
                int cl  = ja2 + q;
                int col = j * 16 + cl;
                float c  = tanhf(y2[i2][q] + bcv[q]);
                float ug = ugs[n * 17 + cl];
                float h0 = h_s[n * 65 + col];
                float hn = ug * h0 + (1.f - ug) * c;
                hst[n * 17 + cl] = hn;
                if (layer == 0)          hout0[n * 64 + col] = hn;
                else if (t == idx_t)     d_last[(size_t)b * 4096 + n * 64 + col] = hn;
            }
        }

        CLUSTER_SYNC();   // S2: h stages visible cluster-wide

        // assemble full h, prime u for next step
        const float* xnext = (t + 1 < T_) ? (xbase + (size_t)(t + 1) * 4096) : 0;
        #pragma unroll 4
        for (int i = tid; i < 4096; i += 256) {
            int n = i >> 6, d = i & 63;
            float hv = ldc_f32(hbase[d >> 4] + (uint32_t)(n * 17 + (d & 15)) * 4);
            h_s[n * 65 + d]       = hv;
            u_s[n * 129 + 64 + d] = hv;
            if (xnext) u_s[n * 129 + d] = xnext[i];
        }
    }
    CLUSTER_SYNC();   // no CTA exits while peers may still read its DSMEM
}

// ---------------------------------------------------------------------------
// Final projection + node max-pool
// ---------------------------------------------------------------------------
__global__ void final_kernel(const float* __restrict__ Wp, const float* __restrict__ bp,
                             float* __restrict__ out)
{
    __shared__ float red[64 * 4];
    const int b = blockIdx.x, n = threadIdx.x;
    const float* h = d_last + (size_t)b * 4096 + n * 64;
    float l0 = bp[0], l1 = bp[1], l2 = bp[2], l3 = bp[3];
    #pragma unroll 8
    for (int d = 0; d < 64; ++d) {
        float v = fmaxf(h[d], 0.f);
        l0 += v * Wp[d * 4 + 0];
        l1 += v * Wp[d * 4 + 1];
        l2 += v * Wp[d * 4 + 2];
        l3 += v * Wp[d * 4 + 3];
    }
    red[n * 4 + 0] = l0; red[n * 4 + 1] = l1; red[n * 4 + 2] = l2; red[n * 4 + 3] = l3;
    __syncthreads();
    for (int s = 32; s > 0; s >>= 1) {
        if (n < s) {
            #pragma unroll
            for (int c = 0; c < 4; ++c)
                red[n * 4 + c] = fmaxf(red[n * 4 + c], red[(n + s) * 4 + c]);
        }
        __syncthreads();
    }
    if (n < 4) out[b * 4 + n] = red[n];
}

// ---------------------------------------------------------------------------
extern "C" void kernel_launch(void* const* d_in, const int* in_sizes, int n_in,
                              void* d_out, int out_size)
{
    (void)in_sizes; (void)n_in; (void)out_size;
    const float* X   = (const float*)d_in[0];
    const int*   len = (const int*)  d_in[1];
    const float* S0  = (const float*)d_in[2];
    const float* S1  = (const float*)d_in[3];
    const float* Wg0 = (const float*)d_in[4];
    const float* bg0 = (const float*)d_in[5];
    const float* Wc0 = (const float*)d_in[6];
    const float* bc0 = (const float*)d_in[7];
    const float* Wg1 = (const float*)d_in[8];
    const float* bg1 = (const float*)d_in[9];
    const float* Wc1 = (const float*)d_in[10];
    const float* bc1 = (const float*)d_in[11];
    const float* Wp  = (const float*)d_in[12];
    const float* bp  = (const float*)d_in[13];
    float* out = (float*)d_out;

    cudaFuncSetAttribute(scan_kernel, cudaFuncAttributeMaxDynamicSharedMemorySize, SMEM_BYTES);

    prep_kernel<<<2, 256>>>(S0, S1);
    scan_kernel<<<128, 256, SMEM_BYTES>>>(X, Wg0, bg0, Wc0, bc0, len, 0);
    scan_kernel<<<128, 256, SMEM_BYTES>>>(X, Wg1, bg1, Wc1, bc1, len, 1);
    final_kernel<<<B_, 64>>>(Wp, bp, out);
}

// round 4
// speedup vs baseline: 2.5444x; 1.2053x over previous
#include <cuda_runtime.h>
#include <math.h>
#include <stdint.h>

#define B_ 32
#define T_ 128

typedef unsigned long long u64t;

// Scratch (device globals: allocation-free)
__device__ float d_M[4 * 4096];                 // S0, 2S0^2-I, S1, 2S1^2-I
__device__ float d_out0[B_ * T_ * 4096];        // layer-0 h states
__device__ float d_last[B_ * 4096];             // layer-1 h at last relevant t
__device__ float d_Gx[(size_t)B_ * T_ * 64 * 128]; // gate x-part preactivations (+bias)
__device__ float d_Cx[(size_t)B_ * T_ * 64 * 64];  // cand x-part preactivations (+bias)

// ---------------- f32x2 helpers ----------------
__device__ __forceinline__ u64t pack_dup(float x) {
    u64t r; asm("mov.b64 %0, {%1,%1};" : "=l"(r) : "f"(x)); return r;
}
__device__ __forceinline__ u64t pack2(float lo, float hi) {
    u64t r; asm("mov.b64 %0, {%1,%2};" : "=l"(r) : "f"(lo), "f"(hi)); return r;
}
__device__ __forceinline__ float2 unpack2(u64t v) {
    float2 f; asm("mov.b64 {%0,%1}, %2;" : "=f"(f.x), "=f"(f.y) : "l"(v)); return f;
}
__device__ __forceinline__ void fma2(u64t& d, u64t a, u64t b) {
    asm("fma.rn.f32x2 %0, %1, %2, %0;" : "+l"(d) : "l"(a), "l"(b));
}

__device__ __forceinline__ uint32_t s_u32(const void* p) {
    return (uint32_t)__cvta_generic_to_shared(p);
}
__device__ __forceinline__ uint32_t mapa_rank(uint32_t a, uint32_t r) {
    uint32_t o;
    asm("mapa.shared::cluster.u32 %0, %1, %2;" : "=r"(o) : "r"(a), "r"(r));
    return o;
}
__device__ __forceinline__ float ldc_f32(uint32_t a) {
    float v;
    asm volatile("ld.shared::cluster.f32 %0, [%1];" : "=f"(v) : "r"(a));
    return v;
}
#define CLUSTER_SYNC() do { \
    asm volatile("barrier.cluster.arrive.aligned;" ::: "memory"); \
    asm volatile("barrier.cluster.wait.aligned;"   ::: "memory"); } while (0)

extern __shared__ float smem[];

// ---------------------------------------------------------------------------
// Precompute diffusion operators.
// ---------------------------------------------------------------------------
__global__ void prep_kernel(const float* __restrict__ S0, const float* __restrict__ S1)
{
    __shared__ float Ss[64 * 64];
    const int s = blockIdx.x;
    const float* S = s ? S1 : S0;
    for (int i = threadIdx.x; i < 4096; i += blockDim.x) Ss[i] = S[i];
    __syncthreads();
    for (int i = threadIdx.x; i < 4096; i += blockDim.x) {
        int m = i >> 6, n = i & 63;
        float acc = 0.f;
        #pragma unroll 8
        for (int p = 0; p < 64; ++p) acc += Ss[m * 64 + p] * Ss[p * 64 + n];
        d_M[(2 * s) * 4096 + i]     = Ss[i];
        d_M[(2 * s + 1) * 4096 + i] = 2.f * acc - (m == n ? 1.f : 0.f);
    }
}

// ---------------------------------------------------------------------------
// Precompute x-contributions for every (b,t):
//   xa_k = M_k x;  Gx = bg + sum_k xa_k @ Wg[k*128 .. k*128+63, :]
//                  Cx = bc + sum_k xa_k @ Wc[k*128 .. k*128+63, :]
// Grid 4096 = (b*T+t), 512 threads.
// smem: x_s 64x68 | xa_s 4x64x68 | Ms 4x64x68
// ---------------------------------------------------------------------------
#define PRE_SMEM_BYTES ((4352 + 17408 + 17408) * 4)

__global__ void __launch_bounds__(512, 1)
pre_kernel(const float* __restrict__ Xin,
           const float* __restrict__ Wg, const float* __restrict__ bg,
           const float* __restrict__ Wc, const float* __restrict__ bc,
           int layer)
{
    float* x_s  = smem;                  // 64*68
    float* xa_s = smem + 4352;           // 4 * 64*68
    float* Ms   = smem + 4352 + 17408;   // 4 * 64*68

    const int tid = threadIdx.x;
    const int bt = blockIdx.x;
    const float* xsrc = (layer ? d_out0 : Xin) + (size_t)bt * 4096;

    for (int i = tid; i < 4096; i += 512)
        x_s[(i >> 6) * 68 + (i & 63)] = xsrc[i];
    for (int i = tid; i < 16384; i += 512) {
        int k = i >> 12, r = (i >> 6) & 63, p = i & 63;
        Ms[k * 4352 + r * 68 + p] = d_M[i];
    }
    __syncthreads();

    // phase 1: xa_k = M_k @ x
    {
        const int r2 = tid >> 4;           // rows {r2, r2+32}
        const int c4 = (tid & 15) * 4;     // 4 cols
        #pragma unroll
        for (int km = 0; km < 4; ++km) {
            const float* Mk = Ms + km * 4352;
            u64t a00 = 0, a01 = 0, a10 = 0, a11 = 0;
            #pragma unroll 4
            for (int p = 0; p < 64; ++p) {
                u64t m0 = pack_dup(Mk[r2 * 68 + p]);
                u64t m1 = pack_dup(Mk[(r2 + 32) * 68 + p]);
                ulonglong2 xv = *(const ulonglong2*)(x_s + p * 68 + c4);
                fma2(a00, m0, xv.x); fma2(a01, m0, xv.y);
                fma2(a10, m1, xv.x); fma2(a11, m1, xv.y);
            }
            ulonglong2 s;
            s.x = a00; s.y = a01;
            *(ulonglong2*)(xa_s + km * 4352 + r2 * 68 + c4) = s;
            s.x = a10; s.y = a11;
            *(ulonglong2*)(xa_s + km * 4352 + (r2 + 32) * 68 + c4) = s;
        }
    }
    __syncthreads();

    const int colg = tid & 15;
    const int rowg = tid >> 4;         // rows {rowg, rowg+32}

    // phase 2 gate: 8 cols per thread
    {
        const int cb = colg * 8;
        u64t acc0[4], acc1[4];
        #pragma unroll
        for (int cp = 0; cp < 4; ++cp) {
            u64t bb = pack2(bg[cb + 2 * cp], bg[cb + 2 * cp + 1]);
            acc0[cp] = bb; acc1[cp] = bb;
        }
        for (int k = 0; k < 5; ++k) {
            const float* A = (k == 0) ? x_s : (xa_s + (k - 1) * 4352);
            const float* Wrow = Wg + (size_t)(k * 128) * 128 + cb;
            #pragma unroll 4
            for (int p = 0; p < 64; ++p) {
                ulonglong2 w0 = *(const ulonglong2*)(Wrow + (size_t)p * 128);
                ulonglong2 w1 = *(const ulonglong2*)(Wrow + (size_t)p * 128 + 4);
                u64t a0 = pack_dup(A[rowg * 68 + p]);
                u64t a1 = pack_dup(A[(rowg + 32) * 68 + p]);
                fma2(acc0[0], a0, w0.x); fma2(acc0[1], a0, w0.y);
                fma2(acc0[2], a0, w1.x); fma2(acc0[3], a0, w1.y);
                fma2(acc1[0], a1, w0.x); fma2(acc1[1], a1, w0.y);
                fma2(acc1[2], a1, w1.x); fma2(acc1[3], a1, w1.y);
            }
        }
        float* gx = d_Gx + (size_t)bt * 8192;
        ulonglong2 s;
        s.x = acc0[0]; s.y = acc0[1]; *(ulonglong2*)(gx + rowg * 128 + cb) = s;
        s.x = acc0[2]; s.y = acc0[3]; *(ulonglong2*)(gx + rowg * 128 + cb + 4) = s;
        s.x = acc1[0]; s.y = acc1[1]; *(ulonglong2*)(gx + (rowg + 32) * 128 + cb) = s;
        s.x = acc1[2]; s.y = acc1[3]; *(ulonglong2*)(gx + (rowg + 32) * 128 + cb + 4) = s;
    }

    // phase 2 cand: 4 cols per thread
    {
        const int cb = colg * 4;
        u64t acc0[2], acc1[2];
        acc0[0] = acc1[0] = pack2(bc[cb], bc[cb + 1]);
        acc0[1] = acc1[1] = pack2(bc[cb + 2], bc[cb + 3]);
        for (int k = 0; k < 5; ++k) {
            const float* A = (k == 0) ? x_s : (xa_s + (k - 1) * 4352);
            const float* Wrow = Wc + (size_t)(k * 128) * 64 + cb;
            #pragma unroll 4
            for (int p = 0; p < 64; ++p) {
                ulonglong2 w = *(const ulonglong2*)(Wrow + (size_t)p * 64);
                u64t a0 = pack_dup(A[rowg * 68 + p]);
                u64t a1 = pack_dup(A[(rowg + 32) * 68 + p]);
                fma2(acc0[0], a0, w.x); fma2(acc0[1], a0, w.y);
                fma2(acc1[0], a1, w.x); fma2(acc1[1], a1, w.y);
            }
        }
        float* cx = d_Cx + (size_t)bt * 4096;
        ulonglong2 s;
        s.x = acc0[0]; s.y = acc0[1]; *(ulonglong2*)(cx + rowg * 64 + cb) = s;
        s.x = acc1[0]; s.y = acc1[1]; *(ulonglong2*)(cx + (rowg + 32) * 64 + cb) = s;
    }
}

// ---------------------------------------------------------------------------
// Persistent per-layer scan (h-half only). Grid 128 = 32 batches x cluster(4).
// smem layout (floats):
//   wg_h 0        (5*64*32 = 10240)   gate h-part weight slice
//   wc_h 10240    (5*64*16 =  5120)   cand h-part weight slice
//   Ms   15360    (4*64*68 = 17408)   all 4 diffusion mats, pitch 68
//   h_s  32768    (64*65   =  4160)
//   rh_s 36928    (64*65   =  4160)
//   V_s  41088    (5*64*36 = 11520)
//   rst  52608    (64*17)   ugs 53696 (64*17)   hst 54784 (64*17)
// total 55872 floats = 223488 B
// ---------------------------------------------------------------------------
#define SCAN_SMEM_BYTES (55872 * 4)

__global__ void __launch_bounds__(256, 1) __cluster_dims__(4, 1, 1)
scan_kernel(const float* __restrict__ Wg, const float* __restrict__ Wc,
            const int* __restrict__ lens, int layer)
{
    float* wg_h = smem;
    float* wc_h = smem + 10240;
    float* Ms   = smem + 15360;
    float* h_s  = smem + 32768;
    float* rh_s = smem + 36928;
    float* V_s  = smem + 41088;
    float* rst  = smem + 52608;
    float* ugs  = smem + 53696;
    float* hst  = smem + 54784;

    const int tid = threadIdx.x;
    const int b = blockIdx.x >> 2;
    const int j = blockIdx.x & 3;

    // one-time loads
    for (int i = tid; i < 10240; i += 256) {           // wg_h[k][d][c] = Wg[k*128+64+d][gmap]
        int k = i >> 11, d = (i >> 5) & 63, c = i & 31;
        int g = (c < 16) ? (j * 16 + c) : (64 + j * 16 + (c - 16));
        wg_h[i] = Wg[(size_t)(k * 128 + 64 + d) * 128 + g];
    }
    for (int i = tid; i < 5120; i += 256) {            // wc_h[k][d][c]
        int k = i >> 10, d = (i >> 4) & 63, c = i & 15;
        wc_h[i] = Wc[(size_t)(k * 128 + 64 + d) * 64 + j * 16 + c];
    }
    for (int i = tid; i < 16384; i += 256) {
        int k = i >> 12, r = (i >> 6) & 63, p = i & 63;
        Ms[k * 4352 + r * 68 + p] = d_M[i];
    }
    for (int i = tid; i < 4096; i += 256)
        h_s[(i >> 6) * 65 + (i & 63)] = 0.f;

    int idx_t = lens[b] - 1;
    idx_t = idx_t < 0 ? 0 : (idx_t > T_ - 1 ? T_ - 1 : idx_t);

    uint32_t rbase[4], hbase[4];
    #pragma unroll
    for (int r = 0; r < 4; ++r) {
        rbase[r] = mapa_rank(s_u32(rst), (uint32_t)r);
        hbase[r] = mapa_rank(s_u32(hst), (uint32_t)r);
    }

    const int rg  = tid & 31;
    const int jg  = tid >> 5;
    const int mg  = tid >> 3;
    const int ja4 = (tid & 7) * 4;
    const int ja2 = (tid & 7) * 2;
    const int g0  = (ja4 < 16) ? (j * 16 + ja4) : (64 + j * 16 + (ja4 - 16));
    const int c0  = j * 16 + ja2;

    const float* gxb = d_Gx + (size_t)b * T_ * 8192;
    const float* cxb = d_Cx + (size_t)b * T_ * 4096;

    for (int t = 0; t < T_; ++t) {
        __syncthreads();

        // prefetch x-contributions for this step
        const float* gx = gxb + (size_t)t * 8192;
        const float* cx = cxb + (size_t)t * 4096;
        float4 gA = __ldg((const float4*)(gx + mg * 128 + g0));
        float4 gB = __ldg((const float4*)(gx + (mg + 32) * 128 + g0));
        float2 cA = __ldg((const float2*)(cx + mg * 64 + c0));
        float2 cB = __ldg((const float2*)(cx + (mg + 32) * 64 + c0));

        // ---------- gate V-phase: V_k = h @ wg_h[k], all 5 k ----------
        {
            u64t acc[5][4];
            #pragma unroll
            for (int k = 0; k < 5; ++k) { acc[k][0] = acc[k][1] = acc[k][2] = acc[k][3] = 0; }
            const float* h0p = h_s + rg * 65;
            const float* h1p = h_s + (rg + 32) * 65;
            const float* wbase = wg_h + jg * 4;
            #pragma unroll 4
            for (int d = 0; d < 64; ++d) {
                u64t a0 = pack_dup(h0p[d]);
                u64t a1 = pack_dup(h1p[d]);
                #pragma unroll
                for (int k = 0; k < 5; ++k) {
                    ulonglong2 w = *(const ulonglong2*)(wbase + k * 2048 + d * 32);
                    fma2(acc[k][0], a0, w.x); fma2(acc[k][1], a0, w.y);
                    fma2(acc[k][2], a1, w.x); fma2(acc[k][3], a1, w.y);
                }
            }
            #pragma unroll
            for (int k = 0; k < 5; ++k) {
                ulonglong2 s;
                s.x = acc[k][0]; s.y = acc[k][1];
                *(ulonglong2*)(V_s + k * 2304 + rg * 36 + jg * 4) = s;
                s.x = acc[k][2]; s.y = acc[k][3];
                *(ulonglong2*)(V_s + k * 2304 + (rg + 32) * 36 + jg * 4) = s;
            }
        }
        __syncthreads();

        // ---------- gate M-apply + sigmoid + stage ----------
        {
            float4 vA = *(const float4*)(V_s + mg * 36 + ja4);
            float4 vB = *(const float4*)(V_s + (mg + 32) * 36 + ja4);
            u64t y00 = pack2(gA.x + vA.x, gA.y + vA.y);
            u64t y01 = pack2(gA.z + vA.z, gA.w + vA.w);
            u64t y10 = pack2(gB.x + vB.x, gB.y + vB.y);
            u64t y11 = pack2(gB.z + vB.z, gB.w + vB.w);
            for (int k = 1; k < 5; ++k) {
                const float* Mk = Ms + (k - 1) * 4352;
                const float* Vk = V_s + k * 2304;
                #pragma unroll 4
                for (int m = 0; m < 64; m += 4) {
                    float4 mA = *(const float4*)(Mk + mg * 68 + m);
                    float4 mB = *(const float4*)(Mk + (mg + 32) * 68 + m);
                    float mAa[4] = {mA.x, mA.y, mA.z, mA.w};
                    float mBa[4] = {mB.x, mB.y, mB.z, mB.w};
                    #pragma unroll
                    for (int q = 0; q < 4; ++q) {
                        ulonglong2 v = *(const ulonglong2*)(Vk + (m + q) * 36 + ja4);
                        u64t da = pack_dup(mAa[q]);
                        u64t db = pack_dup(mBa[q]);
                        fma2(y00, da, v.x); fma2(y01, da, v.y);
                        fma2(y10, db, v.x); fma2(y11, db, v.y);
                    }
                }
            }
            float2 p00 = unpack2(y00), p01 = unpack2(y01);
            float2 p10 = unpack2(y10), p11 = unpack2(y11);
            float v0a[4] = {p00.x, p00.y, p01.x, p01.y};
            float v1a[4] = {p10.x, p10.y, p11.x, p11.y};
            #pragma unroll
            for (int q = 0; q < 4; ++q) {
                int c = ja4 + q;
                float s0 = 1.f / (1.f + expf(-v0a[q]));
                float s1 = 1.f / (1.f + expf(-v1a[q]));
                if (c < 16) { rst[mg * 17 + c] = s0;        rst[(mg + 32) * 17 + c] = s1; }
                else        { ugs[mg * 17 + c - 16] = s0;   ugs[(mg + 32) * 17 + c - 16] = s1; }
            }
        }

        CLUSTER_SYNC();   // r stages visible cluster-wide

        // rh = r * h (r gathered via DSMEM)
        #pragma unroll 4
        for (int i = tid; i < 4096; i += 256) {
            int n = i >> 6, d = i & 63;
            float r = ldc_f32(rbase[d >> 4] + (uint32_t)(n * 17 + (d & 15)) * 4);
            rh_s[n * 65 + d] = r * h_s[n * 65 + d];
        }
        __syncthreads();

        // ---------- cand V-phase ----------
        {
            u64t acc[5][2];
            #pragma unroll
            for (int k = 0; k < 5; ++k) { acc[k][0] = acc[k][1] = 0; }
            const float* h0p = rh_s + rg * 65;
            const float* h1p = rh_s + (rg + 32) * 65;
            const float* wbase = wc_h + jg * 2;
            #pragma unroll 4
            for (int d = 0; d < 64; ++d) {
                u64t a0 = pack_dup(h0p[d]);
                u64t a1 = pack_dup(h1p[d]);
                #pragma unroll
                for (int k = 0; k < 5; ++k) {
                    u64t w = *(const u64t*)(wbase + k * 1024 + d * 16);
                    fma2(acc[k][0], a0, w);
                    fma2(acc[k][1], a1, w);
                }
            }
            #pragma unroll
            for (int k = 0; k < 5; ++k) {
                *(u64t*)(V_s + k * 2304 + rg * 36 + jg * 2)        = acc[k][0];
                *(u64t*)(V_s + k * 2304 + (rg + 32) * 36 + jg * 2) = acc[k][1];
            }
        }
        __syncthreads();

        // ---------- cand M-apply + GRU update ----------
        {
            float2 v0 = *(const float2*)(V_s + mg * 36 + ja2);
            float2 v1 = *(const float2*)(V_s + (mg + 32) * 36 + ja2);
            u64t y0 = pack2(cA.x + v0.x, cA.y + v0.y);
            u64t y1 = pack2(cB.x + v1.x, cB.y + v1.y);
            for (int k = 1; k < 5; ++k) {
                const float* Mk = Ms + (k - 1) * 4352;
                const float* Vk = V_s + k * 2304;
                #pragma unroll 4
                for (int m = 0; m < 64; m += 4) {
                    float4 mA = *(const float4*)(Mk + mg * 68 + m);
                    float4 mB = *(const float4*)(Mk + (mg + 32) * 68 + m);
                    float mAa[4] = {mA.x, mA.y, mA.z, mA.w};
                    float mBa[4] = {mB.x, mB.y, mB.z, mB.w};
                    #pragma unroll
                    for (int q = 0; q < 4; ++q) {
                        u64t v = *(const u64t*)(Vk + (m + q) * 36 + ja2);
                        fma2(y0, pack_dup(mAa[q]), v);
                        fma2(y1, pack_dup(mBa[q]), v);
                    }
                }
            }
            float* hout0 = d_out0 + ((size_t)(b * T_ + t)) * 4096;
            float2 cc0 = unpack2(y0), cc1 = unpack2(y1);
            float cand0[2] = {cc0.x, cc0.y};
            float cand1[2] = {cc1.x, cc1.y};
            #pragma unroll
            for (int q = 0; q < 2; ++q) {
                int cl = ja2 + q;
                int col = j * 16 + cl;
                float cv0 = tanhf(cand0[q]);
                float ug0 = ugs[mg * 17 + cl];
                float hn0 = ug0 * h_s[mg * 65 + col] + (1.f - ug0) * cv0;
                hst[mg * 17 + cl] = hn0;
                float cv1 = tanhf(cand1[q]);
                float ug1 = ugs[(mg + 32) * 17 + cl];
                float hn1 = ug1 * h_s[(mg + 32) * 65 + col] + (1.f - ug1) * cv1;
                hst[(mg + 32) * 17 + cl] = hn1;
                if (layer == 0) {
                    hout0[mg * 64 + col]        = hn0;
                    hout0[(mg + 32) * 64 + col] = hn1;
                } else if (t == idx_t) {
                    d_last[(size_t)b * 4096 + mg * 64 + col]        = hn0;
                    d_last[(size_t)b * 4096 + (mg + 32) * 64 + col] = hn1;
                }
            }
        }

        CLUSTER_SYNC();   // h stages visible cluster-wide

        // assemble full h for next step
        #pragma unroll 4
        for (int i = tid; i < 4096; i += 256) {
            int n = i >> 6, d = i & 63;
            h_s[n * 65 + d] = ldc_f32(hbase[d >> 4] + (uint32_t)(n * 17 + (d & 15)) * 4);
        }
    }
    CLUSTER_SYNC();   // no CTA exits while peers may still read its DSMEM
}

// ---------------------------------------------------------------------------
// Final projection + node max-pool
// ---------------------------------------------------------------------------
__global__ void final_kernel(const float* __restrict__ Wp, const float* __restrict__ bp,
                             float* __restrict__ out)
{
    __shared__ float red[64 * 4];
    const int b = blockIdx.x, n = threadIdx.x;
    const float* h = d_last + (size_t)b * 4096 + n * 64;
    float l0 = bp[0], l1 = bp[1], l2 = bp[2], l3 = bp[3];
    #pragma unroll 8
    for (int d = 0; d < 64; ++d) {
        float v = fmaxf(h[d], 0.f);
        l0 += v * Wp[d * 4 + 0];
        l1 += v * Wp[d * 4 + 1];
        l2 += v * Wp[d * 4 + 2];
        l3 += v * Wp[d * 4 + 3];
    }
    red[n * 4 + 0] = l0; red[n * 4 + 1] = l1; red[n * 4 + 2] = l2; red[n * 4 + 3] = l3;
    __syncthreads();
    for (int s = 32; s > 0; s >>= 1) {
        if (n < s) {
            #pragma unroll
            for (int c = 0; c < 4; ++c)
                red[n * 4 + c] = fmaxf(red[n * 4 + c], red[(n + s) * 4 + c]);
        }
        __syncthreads();
    }
    if (n < 4) out[b * 4 + n] = red[n];
}

// ---------------------------------------------------------------------------
extern "C" void kernel_launch(void* const* d_in, const int* in_sizes, int n_in,
                              void* d_out, int out_size)
{
    (void)in_sizes; (void)n_in; (void)out_size;
    const float* X   = (const float*)d_in[0];
    const int*   len = (const int*)  d_in[1];
    const float* S0  = (const float*)d_in[2];
    const float* S1  = (const float*)d_in[3];
    const float* Wg0 = (const float*)d_in[4];
    const float* bg0 = (const float*)d_in[5];
    const float* Wc0 = (const float*)d_in[6];
    const float* bc0 = (const float*)d_in[7];
    const float* Wg1 = (const float*)d_in[8];
    const float* bg1 = (const float*)d_in[9];
    const float* Wc1 = (const float*)d_in[10];
    const float* bc1 = (const float*)d_in[11];
    const float* Wp  = (const float*)d_in[12];
    const float* bp  = (const float*)d_in[13];
    float* out = (float*)d_out;

    cudaFuncSetAttribute(pre_kernel,  cudaFuncAttributeMaxDynamicSharedMemorySize, PRE_SMEM_BYTES);
    cudaFuncSetAttribute(scan_kernel, cudaFuncAttributeMaxDynamicSharedMemorySize, SCAN_SMEM_BYTES);

    prep_kernel<<<2, 256>>>(S0, S1);
    pre_kernel<<<B_ * T_, 512, PRE_SMEM_BYTES>>>(X, Wg0, bg0, Wc0, bc0, 0);
    scan_kernel<<<128, 256, SCAN_SMEM_BYTES>>>(Wg0, Wc0, len, 0);
    pre_kernel<<<B_ * T_, 512, PRE_SMEM_BYTES>>>(X, Wg1, bg1, Wc1, bc1, 1);
    scan_kernel<<<128, 256, SCAN_SMEM_BYTES>>>(Wg1, Wc1, len, 1);
    final_kernel<<<B_, 64>>>(Wp, bp, out);
}

// round 5
// speedup vs baseline: 2.9248x; 1.1495x over previous
#include <cuda_runtime.h>
#include <math.h>
#include <stdint.h>

#define B_ 32
#define T_ 128

typedef unsigned long long u64t;

// Scratch (device globals: allocation-free)
__device__ float d_M[4 * 4096];                 // S0, 2S0^2-I, S1, 2S1^2-I
__device__ float d_out0[B_ * T_ * 4096];        // layer-0 h states
__device__ float d_last[B_ * 4096];             // layer-1 h at last relevant t
__device__ float d_Gx[(size_t)B_ * T_ * 64 * 128]; // gate x-part preactivations (+bias)
__device__ float d_Cx[(size_t)B_ * T_ * 64 * 64];  // cand x-part preactivations (+bias)

// ---------------- f32x2 helpers ----------------
__device__ __forceinline__ u64t pack_dup(float x) {
    u64t r; asm("mov.b64 %0, {%1,%1};" : "=l"(r) : "f"(x)); return r;
}
__device__ __forceinline__ u64t pack2(float lo, float hi) {
    u64t r; asm("mov.b64 %0, {%1,%2};" : "=l"(r) : "f"(lo), "f"(hi)); return r;
}
__device__ __forceinline__ float2 unpack2(u64t v) {
    float2 f; asm("mov.b64 {%0,%1}, %2;" : "=f"(f.x), "=f"(f.y) : "l"(v)); return f;
}
__device__ __forceinline__ void fma2(u64t& d, u64t a, u64t b) {
    asm("fma.rn.f32x2 %0, %1, %2, %0;" : "+l"(d) : "l"(a), "l"(b));
}

__device__ __forceinline__ uint32_t s_u32(const void* p) {
    return (uint32_t)__cvta_generic_to_shared(p);
}
__device__ __forceinline__ uint32_t mapa_rank(uint32_t a, uint32_t r) {
    uint32_t o;
    asm("mapa.shared::cluster.u32 %0, %1, %2;" : "=r"(o) : "r"(a), "r"(r));
    return o;
}
__device__ __forceinline__ float ldc_f32(uint32_t a) {
    float v;
    asm volatile("ld.shared::cluster.f32 %0, [%1];" : "=f"(v) : "r"(a));
    return v;
}
#define CLUSTER_SYNC() do { \
    asm volatile("barrier.cluster.arrive.aligned;" ::: "memory"); \
    asm volatile("barrier.cluster.wait.aligned;"   ::: "memory"); } while (0)

extern __shared__ float smem[];

// ---------------------------------------------------------------------------
// Precompute diffusion operators.
// ---------------------------------------------------------------------------
__global__ void prep_kernel(const float* __restrict__ S0, const float* __restrict__ S1)
{
    __shared__ float Ss[64 * 64];
    const int s = blockIdx.x;
    const float* S = s ? S1 : S0;
    for (int i = threadIdx.x; i < 4096; i += blockDim.x) Ss[i] = S[i];
    __syncthreads();
    for (int i = threadIdx.x; i < 4096; i += blockDim.x) {
        int m = i >> 6, n = i & 63;
        float acc = 0.f;
        #pragma unroll 8
        for (int p = 0; p < 64; ++p) acc += Ss[m * 64 + p] * Ss[p * 64 + n];
        d_M[(2 * s) * 4096 + i]     = Ss[i];
        d_M[(2 * s + 1) * 4096 + i] = 2.f * acc - (m == n ? 1.f : 0.f);
    }
}

// ---------------------------------------------------------------------------
// Precompute x-contributions for every (b,t):
//   xa_k = M_k x;  Gx = bg + sum_k xa_k @ Wg[k*128 .. k*128+63, :]
//                  Cx = bc + sum_k xa_k @ Wc[k*128 .. k*128+63, :]
// Grid 4096 = (b*T+t), 512 threads.
// Mapping: warp = output-column group (uniform W -> broadcast loads),
//          lane = row pair {r0, r0+32}. A in smem pitch 68, read via LDS.128.
// smem: x_s 64x68 | xa_s 4x64x68 | Ms 4x64x68  (pitch 68: 16B aligned, and
// stride 272B is conflict-free for lane-varying LDS.128)
// ---------------------------------------------------------------------------
#define PRE_SMEM_BYTES (4352 * 9 * 4)

__global__ void __launch_bounds__(512, 1)
pre_kernel(const float* __restrict__ Xin,
           const float* __restrict__ Wg, const float* __restrict__ bg,
           const float* __restrict__ Wc, const float* __restrict__ bc,
           int layer)
{
    float* x_s  = smem;                  // 64*68
    float* xa_s = smem + 4352;           // 4 * 64*68
    float* Ms   = smem + 4352 * 5;       // 4 * 64*68

    const int tid = threadIdx.x;
    const int bt = blockIdx.x;
    const int r0 = tid & 31;             // rows {r0, r0+32}
    const int g  = tid >> 5;             // warp id 0..15 (uniform per warp)

    const float* xsrc = (layer ? d_out0 : Xin) + (size_t)bt * 4096;

    for (int i = tid; i < 4096; i += 512)
        x_s[(i >> 6) * 68 + (i & 63)] = xsrc[i];
    for (int i = tid; i < 16384; i += 512) {
        int k = i >> 12, r = (i >> 6) & 63, p = i & 63;
        Ms[k * 4352 + r * 68 + p] = d_M[i];
    }
    __syncthreads();

    // ---------------- phase 1: xa_k = M_k @ x ----------------
    // thread: rows {r0, r0+32}, cols [g*4, g*4+4)
    {
        const int c4 = g * 4;
        #pragma unroll
        for (int k = 0; k < 4; ++k) {
            const float* Mk = Ms + k * 4352;
            u64t a00 = 0, a01 = 0, a10 = 0, a11 = 0;
            #pragma unroll 4
            for (int n4 = 0; n4 < 64; n4 += 4) {
                float4 m0 = *(const float4*)(Mk + r0 * 68 + n4);
                float4 m1 = *(const float4*)(Mk + (r0 + 32) * 68 + n4);
                float m0a[4] = {m0.x, m0.y, m0.z, m0.w};
                float m1a[4] = {m1.x, m1.y, m1.z, m1.w};
                #pragma unroll
                for (int q = 0; q < 4; ++q) {
                    ulonglong2 xv = *(const ulonglong2*)(x_s + (n4 + q) * 68 + c4);
                    u64t d0 = pack_dup(m0a[q]);
                    u64t d1 = pack_dup(m1a[q]);
                    fma2(a00, d0, xv.x); fma2(a01, d0, xv.y);
                    fma2(a10, d1, xv.x); fma2(a11, d1, xv.y);
                }
            }
            ulonglong2 s;
            s.x = a00; s.y = a01;
            *(ulonglong2*)(xa_s + k * 4352 + r0 * 68 + c4) = s;
            s.x = a10; s.y = a11;
            *(ulonglong2*)(xa_s + k * 4352 + (r0 + 32) * 68 + c4) = s;
        }
    }
    __syncthreads();

    // ---------------- phase 2: Gx / Cx (merged, A loaded once) ----------------
    // thread: rows {r0, r0+32}; gate cols [g*8, g*8+8); cand cols [g*4, g*4+4)
    {
        const int gb = g * 8;
        const int cb = g * 4;
        u64t ag0[4], ag1[4], ac0[2], ac1[2];
        #pragma unroll
        for (int q = 0; q < 4; ++q) {
            u64t bb = pack2(bg[gb + 2 * q], bg[gb + 2 * q + 1]);
            ag0[q] = bb; ag1[q] = bb;
        }
        ac0[0] = ac1[0] = pack2(bc[cb], bc[cb + 1]);
        ac0[1] = ac1[1] = pack2(bc[cb + 2], bc[cb + 3]);

        for (int k = 0; k < 5; ++k) {
            const float* A = (k == 0) ? x_s : (xa_s + (k - 1) * 4352);
            const float* WgK = Wg + (size_t)(k * 128) * 128 + gb;
            const float* WcK = Wc + (size_t)(k * 128) * 64 + cb;
            #pragma unroll 2
            for (int p4 = 0; p4 < 64; p4 += 4) {
                float4 a0 = *(const float4*)(A + r0 * 68 + p4);
                float4 a1 = *(const float4*)(A + (r0 + 32) * 68 + p4);
                float a0a[4] = {a0.x, a0.y, a0.z, a0.w};
                float a1a[4] = {a1.x, a1.y, a1.z, a1.w};
                #pragma unroll
                for (int q = 0; q < 4; ++q) {
                    const int p = p4 + q;
                    ulonglong2 w0 = *(const ulonglong2*)(WgK + (size_t)p * 128);
                    ulonglong2 w1 = *(const ulonglong2*)(WgK + (size_t)p * 128 + 4);
                    ulonglong2 wc = *(const ulonglong2*)(WcK + (size_t)p * 64);
                    u64t d0 = pack_dup(a0a[q]);
                    u64t d1 = pack_dup(a1a[q]);
                    fma2(ag0[0], d0, w0.x); fma2(ag0[1], d0, w0.y);
                    fma2(ag0[2], d0, w1.x); fma2(ag0[3], d0, w1.y);
                    fma2(ag1[0], d1, w0.x); fma2(ag1[1], d1, w0.y);
                    fma2(ag1[2], d1, w1.x); fma2(ag1[3], d1, w1.y);
                    fma2(ac0[0], d0, wc.x); fma2(ac0[1], d0, wc.y);
                    fma2(ac1[0], d1, wc.x); fma2(ac1[1], d1, wc.y);
                }
            }
        }

        float* gx = d_Gx + (size_t)bt * 8192;
        float* cx = d_Cx + (size_t)bt * 4096;
        ulonglong2 s;
        s.x = ag0[0]; s.y = ag0[1]; *(ulonglong2*)(gx + r0 * 128 + gb) = s;
        s.x = ag0[2]; s.y = ag0[3]; *(ulonglong2*)(gx + r0 * 128 + gb + 4) = s;
        s.x = ag1[0]; s.y = ag1[1]; *(ulonglong2*)(gx + (r0 + 32) * 128 + gb) = s;
        s.x = ag1[2]; s.y = ag1[3]; *(ulonglong2*)(gx + (r0 + 32) * 128 + gb + 4) = s;
        s.x = ac0[0]; s.y = ac0[1]; *(ulonglong2*)(cx + r0 * 64 + cb) = s;
        s.x = ac1[0]; s.y = ac1[1]; *(ulonglong2*)(cx + (r0 + 32) * 64 + cb) = s;
    }
}

// ---------------------------------------------------------------------------
// Persistent per-layer scan (h-half only). Grid 128 = 32 batches x cluster(4).
// (unchanged from R4 — known correct, ~fma2-issue-bound)
// ---------------------------------------------------------------------------
#define SCAN_SMEM_BYTES (55872 * 4)

__global__ void __launch_bounds__(256, 1) __cluster_dims__(4, 1, 1)
scan_kernel(const float* __restrict__ Wg, const float* __restrict__ Wc,
            const int* __restrict__ lens, int layer)
{
    float* wg_h = smem;
    float* wc_h = smem + 10240;
    float* Ms   = smem + 15360;
    float* h_s  = smem + 32768;
    float* rh_s = smem + 36928;
    float* V_s  = smem + 41088;
    float* rst  = smem + 52608;
    float* ugs  = smem + 53696;
    float* hst  = smem + 54784;

    const int tid = threadIdx.x;
    const int b = blockIdx.x >> 2;
    const int j = blockIdx.x & 3;

    // one-time loads
    for (int i = tid; i < 10240; i += 256) {           // wg_h[k][d][c] = Wg[k*128+64+d][gmap]
        int k = i >> 11, d = (i >> 5) & 63, c = i & 31;
        int g = (c < 16) ? (j * 16 + c) : (64 + j * 16 + (c - 16));
        wg_h[i] = Wg[(size_t)(k * 128 + 64 + d) * 128 + g];
    }
    for (int i = tid; i < 5120; i += 256) {            // wc_h[k][d][c]
        int k = i >> 10, d = (i >> 4) & 63, c = i & 15;
        wc_h[i] = Wc[(size_t)(k * 128 + 64 + d) * 64 + j * 16 + c];
    }
    for (int i = tid; i < 16384; i += 256) {
        int k = i >> 12, r = (i >> 6) & 63, p = i & 63;
        Ms[k * 4352 + r * 68 + p] = d_M[i];
    }
    for (int i = tid; i < 4096; i += 256)
        h_s[(i >> 6) * 65 + (i & 63)] = 0.f;

    int idx_t = lens[b] - 1;
    idx_t = idx_t < 0 ? 0 : (idx_t > T_ - 1 ? T_ - 1 : idx_t);

    uint32_t rbase[4], hbase[4];
    #pragma unroll
    for (int r = 0; r < 4; ++r) {
        rbase[r] = mapa_rank(s_u32(rst), (uint32_t)r);
        hbase[r] = mapa_rank(s_u32(hst), (uint32_t)r);
    }

    const int rg  = tid & 31;
    const int jg  = tid >> 5;
    const int mg  = tid >> 3;
    const int ja4 = (tid & 7) * 4;
    const int ja2 = (tid & 7) * 2;
    const int g0  = (ja4 < 16) ? (j * 16 + ja4) : (64 + j * 16 + (ja4 - 16));
    const int c0  = j * 16 + ja2;

    const float* gxb = d_Gx + (size_t)b * T_ * 8192;
    const float* cxb = d_Cx + (size_t)b * T_ * 4096;

    for (int t = 0; t < T_; ++t) {
        __syncthreads();

        // prefetch x-contributions for this step
        const float* gx = gxb + (size_t)t * 8192;
        const float* cx = cxb + (size_t)t * 4096;
        float4 gA = __ldg((const float4*)(gx + mg * 128 + g0));
        float4 gB = __ldg((const float4*)(gx + (mg + 32) * 128 + g0));
        float2 cA = __ldg((const float2*)(cx + mg * 64 + c0));
        float2 cB = __ldg((const float2*)(cx + (mg + 32) * 64 + c0));

        // ---------- gate V-phase: V_k = h @ wg_h[k], all 5 k ----------
        {
            u64t acc[5][4];
            #pragma unroll
            for (int k = 0; k < 5; ++k) { acc[k][0] = acc[k][1] = acc[k][2] = acc[k][3] = 0; }
            const float* h0p = h_s + rg * 65;
            const float* h1p = h_s + (rg + 32) * 65;
            const float* wbase = wg_h + jg * 4;
            #pragma unroll 4
            for (int d = 0; d < 64; ++d) {
                u64t a0 = pack_dup(h0p[d]);
                u64t a1 = pack_dup(h1p[d]);
                #pragma unroll
                for (int k = 0; k < 5; ++k) {
                    ulonglong2 w = *(const ulonglong2*)(wbase + k * 2048 + d * 32);
                    fma2(acc[k][0], a0, w.x); fma2(acc[k][1], a0, w.y);
                    fma2(acc[k][2], a1, w.x); fma2(acc[k][3], a1, w.y);
                }
            }
            #pragma unroll
            for (int k = 0; k < 5; ++k) {
                ulonglong2 s;
                s.x = acc[k][0]; s.y = acc[k][1];
                *(ulonglong2*)(V_s + k * 2304 + rg * 36 + jg * 4) = s;
                s.x = acc[k][2]; s.y = acc[k][3];
                *(ulonglong2*)(V_s + k * 2304 + (rg + 32) * 36 + jg * 4) = s;
            }
        }
        __syncthreads();

        // ---------- gate M-apply + sigmoid + stage ----------
        {
            float4 vA = *(const float4*)(V_s + mg * 36 + ja4);
            float4 vB = *(const float4*)(V_s + (mg + 32) * 36 + ja4);
            u64t y00 = pack2(gA.x + vA.x, gA.y + vA.y);
            u64t y01 = pack2(gA.z + vA.z, gA.w + vA.w);
            u64t y10 = pack2(gB.x + vB.x, gB.y + vB.y);
            u64t y11 = pack2(gB.z + vB.z, gB.w + vB.w);
            for (int k = 1; k < 5; ++k) {
                const float* Mk = Ms + (k - 1) * 4352;
                const float* Vk = V_s + k * 2304;
                #pragma unroll 4
                for (int m = 0; m < 64; m += 4) {
                    float4 mA = *(const float4*)(Mk + mg * 68 + m);
                    float4 mB = *(const float4*)(Mk + (mg + 32) * 68 + m);
                    float mAa[4] = {mA.x, mA.y, mA.z, mA.w};
                    float mBa[4] = {mB.x, mB.y, mB.z, mB.w};
                    #pragma unroll
                    for (int q = 0; q < 4; ++q) {
                        ulonglong2 v = *(const ulonglong2*)(Vk + (m + q) * 36 + ja4);
                        u64t da = pack_dup(mAa[q]);
                        u64t db = pack_dup(mBa[q]);
                        fma2(y00, da, v.x); fma2(y01, da, v.y);
                        fma2(y10, db, v.x); fma2(y11, db, v.y);
                    }
                }
            }
            float2 p00 = unpack2(y00), p01 = unpack2(y01);
            float2 p10 = unpack2(y10), p11 = unpack2(y11);
            float v0a[4] = {p00.x, p00.y, p01.x, p01.y};
            float v1a[4] = {p10.x, p10.y, p11.x, p11.y};
            #pragma unroll
            for (int q = 0; q < 4; ++q) {
                int c = ja4 + q;
                float s0 = 1.f / (1.f + expf(-v0a[q]));
                float s1 = 1.f / (1.f + expf(-v1a[q]));
                if (c < 16) { rst[mg * 17 + c] = s0;        rst[(mg + 32) * 17 + c] = s1; }
                else        { ugs[mg * 17 + c - 16] = s0;   ugs[(mg + 32) * 17 + c - 16] = s1; }
            }
        }

        CLUSTER_SYNC();   // r stages visible cluster-wide

        // rh = r * h (r gathered via DSMEM)
        #pragma unroll 4
        for (int i = tid; i < 4096; i += 256) {
            int n = i >> 6, d = i & 63;
            float r = ldc_f32(rbase[d >> 4] + (uint32_t)(n * 17 + (d & 15)) * 4);
            rh_s[n * 65 + d] = r * h_s[n * 65 + d];
        }
        __syncthreads();

        // ---------- cand V-phase ----------
        {
            u64t acc[5][2];
            #pragma unroll
            for (int k = 0; k < 5; ++k) { acc[k][0] = acc[k][1] = 0; }
            const float* h0p = rh_s + rg * 65;
            const float* h1p = rh_s + (rg + 32) * 65;
            const float* wbase = wc_h + jg * 2;
            #pragma unroll 4
            for (int d = 0; d < 64; ++d) {
                u64t a0 = pack_dup(h0p[d]);
                u64t a1 = pack_dup(h1p[d]);
                #pragma unroll
                for (int k = 0; k < 5; ++k) {
                    u64t w = *(const u64t*)(wbase + k * 1024 + d * 16);
                    fma2(acc[k][0], a0, w);
                    fma2(acc[k][1], a1, w);
                }
            }
            #pragma unroll
            for (int k = 0; k < 5; ++k) {
                *(u64t*)(V_s + k * 2304 + rg * 36 + jg * 2)        = acc[k][0];
                *(u64t*)(V_s + k * 2304 + (rg + 32) * 36 + jg * 2) = acc[k][1];
            }
        }
        __syncthreads();

        // ---------- cand M-apply + GRU update ----------
        {
            float2 v0 = *(const float2*)(V_s + mg * 36 + ja2);
            float2 v1 = *(const float2*)(V_s + (mg + 32) * 36 + ja2);
            u64t y0 = pack2(cA.x + v0.x, cA.y + v0.y);
            u64t y1 = pack2(cB.x + v1.x, cB.y + v1.y);
            for (int k = 1; k < 5; ++k) {
                const float* Mk = Ms + (k - 1) * 4352;
                const float* Vk = V_s + k * 2304;
                #pragma unroll 4
                for (int m = 0; m < 64; m += 4) {
                    float4 mA = *(const float4*)(Mk + mg * 68 + m);
                    float4 mB = *(const float4*)(Mk + (mg + 32) * 68 + m);
                    float mAa[4] = {mA.x, mA.y, mA.z, mA.w};
                    float mBa[4] = {mB.x, mB.y, mB.z, mB.w};
                    #pragma unroll
                    for (int q = 0; q < 4; ++q) {
                        u64t v = *(const u64t*)(Vk + (m + q) * 36 + ja2);
                        fma2(y0, pack_dup(mAa[q]), v);
                        fma2(y1, pack_dup(mBa[q]), v);
                    }
                }
            }
            float* hout0 = d_out0 + ((size_t)(b * T_ + t)) * 4096;
            float2 cc0 = unpack2(y0), cc1 = unpack2(y1);
            float cand0[2] = {cc0.x, cc0.y};
            float cand1[2] = {cc1.x, cc1.y};
            #pragma unroll
            for (int q = 0; q < 2; ++q) {
                int cl = ja2 + q;
                int col = j * 16 + cl;
                float cv0 = tanhf(cand0[q]);
                float ug0 = ugs[mg * 17 + cl];
                float hn0 = ug0 * h_s[mg * 65 + col] + (1.f - ug0) * cv0;
                hst[mg * 17 + cl] = hn0;
                float cv1 = tanhf(cand1[q]);
                float ug1 = ugs[(mg + 32) * 17 + cl];
                float hn1 = ug1 * h_s[(mg + 32) * 65 + col] + (1.f - ug1) * cv1;
                hst[(mg + 32) * 17 + cl] = hn1;
                if (layer == 0) {
                    hout0[mg * 64 + col]        = hn0;
                    hout0[(mg + 32) * 64 + col] = hn1;
                } else if (t == idx_t) {
                    d_last[(size_t)b * 4096 + mg * 64 + col]        = hn0;
                    d_last[(size_t)b * 4096 + (mg + 32) * 64 + col] = hn1;
                }
            }
        }

        CLUSTER_SYNC();   // h stages visible cluster-wide

        // assemble full h for next step
        #pragma unroll 4
        for (int i = tid; i < 4096; i += 256) {
            int n = i >> 6, d = i & 63;
            h_s[n * 65 + d] = ldc_f32(hbase[d >> 4] + (uint32_t)(n * 17 + (d & 15)) * 4);
        }
    }
    CLUSTER_SYNC();   // no CTA exits while peers may still read its DSMEM
}

// ---------------------------------------------------------------------------
// Final projection + node max-pool
// ---------------------------------------------------------------------------
__global__ void final_kernel(const float* __restrict__ Wp, const float* __restrict__ bp,
                             float* __restrict__ out)
{
    __shared__ float red[64 * 4];
    const int b = blockIdx.x, n = threadIdx.x;
    const float* h = d_last + (size_t)b * 4096 + n * 64;
    float l0 = bp[0], l1 = bp[1], l2 = bp[2], l3 = bp[3];
    #pragma unroll 8
    for (int d = 0; d < 64; ++d) {
        float v = fmaxf(h[d], 0.f);
        l0 += v * Wp[d * 4 + 0];
        l1 += v * Wp[d * 4 + 1];
        l2 += v * Wp[d * 4 + 2];
        l3 += v * Wp[d * 4 + 3];
    }
    red[n * 4 + 0] = l0; red[n * 4 + 1] = l1; red[n * 4 + 2] = l2; red[n * 4 + 3] = l3;
    __syncthreads();
    for (int s = 32; s > 0; s >>= 1) {
        if (n < s) {
            #pragma unroll
            for (int c = 0; c < 4; ++c)
                red[n * 4 + c] = fmaxf(red[n * 4 + c], red[(n + s) * 4 + c]);
        }
        __syncthreads();
    }
    if (n < 4) out[b * 4 + n] = red[n];
}

// ---------------------------------------------------------------------------
extern "C" void kernel_launch(void* const* d_in, const int* in_sizes, int n_in,
                              void* d_out, int out_size)
{
    (void)in_sizes; (void)n_in; (void)out_size;
    const float* X   = (const float*)d_in[0];
    const int*   len = (const int*)  d_in[1];
    const float* S0  = (const float*)d_in[2];
    const float* S1  = (const float*)d_in[3];
    const float* Wg0 = (const float*)d_in[4];
    const float* bg0 = (const float*)d_in[5];
    const float* Wc0 = (const float*)d_in[6];
    const float* bc0 = (const float*)d_in[7];
    const float* Wg1 = (const float*)d_in[8];
    const float* bg1 = (const float*)d_in[9];
    const float* Wc1 = (const float*)d_in[10];
    const float* bc1 = (const float*)d_in[11];
    const float* Wp  = (const float*)d_in[12];
    const float* bp  = (const float*)d_in[13];
    float* out = (float*)d_out;

    cudaFuncSetAttribute(pre_kernel,  cudaFuncAttributeMaxDynamicSharedMemorySize, PRE_SMEM_BYTES);
    cudaFuncSetAttribute(scan_kernel, cudaFuncAttributeMaxDynamicSharedMemorySize, SCAN_SMEM_BYTES);

    prep_kernel<<<2, 256>>>(S0, S1);
    pre_kernel<<<B_ * T_, 512, PRE_SMEM_BYTES>>>(X, Wg0, bg0, Wc0, bc0, 0);
    scan_kernel<<<128, 256, SCAN_SMEM_BYTES>>>(Wg0, Wc0, len, 0);
    pre_kernel<<<B_ * T_, 512, PRE_SMEM_BYTES>>>(X, Wg1, bg1, Wc1, bc1, 1);
    scan_kernel<<<128, 256, SCAN_SMEM_BYTES>>>(Wg1, Wc1, len, 1);
    final_kernel<<<B_, 64>>>(Wp, bp, out);
}